// round 7
// baseline (speedup 1.0000x reference)
#include <cuda_runtime.h>
#include <cuda_bf16.h>
#include <cstdint>

#define NN 3072
#define PP 4
#define FF 64
#define INF_ 256
#define LALPHA 0.2f
#define JHALF 1536
#define FCH 32
#define NCH (JHALF / FCH)      // 48
#define CHW 48                 // prefix chunk width (3072 = 64*48)
#define MAXBAD 1024

// ---------------- device scratch ----------------
__device__ float g_Wh[NN * FF];
__device__ float g_s1[NN];
__device__ float g_s2[NN];
__device__ float g_rs[PP * NN];
__device__ float g_cs[PP * NN];
__device__ float g_u[PP * NN];               // (lamb - rs) * inv_r
__device__ float g_v[PP * NN];               // (lamb - cs) * inv_l
__device__ float g_par[PP * 2];              // [p*2] = inv_l
__device__ __nv_bfloat16 g_whT_h[FF * NN];   // Wh^T bf16 hi [f][j]
__device__ __nv_bfloat16 g_whT_l[FF * NN];   // residual lo
__device__ float g_ss[NN];                   // s2 sorted desc
__device__ int   g_perm[NN];                 // sort permutation
__device__ float g_local[PP * NN * FF];      // in-chunk exclusive prefix of v*Wh
__device__ float g_tot[PP * 64 * FF];        // chunk totals
__device__ float g_offs[PP * 65 * FF];       // scanned chunk offsets
__device__ float g_G1[2 * PP * NN * FF];     // pos GEMM partials (per j-half)
__device__ float g_G2[2 * PP * NN * FF];     // neg GEMM partials
__device__ int g_badcnt;
__device__ unsigned g_bad[MAXBAD];
__device__ float g_e[(size_t)PP * NN * NN];  // fallback e storage

__device__ __forceinline__ uint32_t smem_u32(const void* p) {
    uint32_t a;
    asm("{ .reg .u64 t; cvta.to.shared.u64 t, %1; cvt.u32.u64 %0, t; }" : "=r"(a) : "l"(p));
    return a;
}
__device__ __forceinline__ void cp_async16(uint32_t dst, const void* src) {
    asm volatile("cp.async.cg.shared.global [%0], [%1], 16;" :: "r"(dst), "l"(src) : "memory");
}
#define CP_COMMIT() asm volatile("cp.async.commit_group;" ::: "memory")
#define CP_WAIT(N)  asm volatile("cp.async.wait_group %0;" :: "n"(N) : "memory")
__device__ __forceinline__ void ldsm4(uint32_t& r0, uint32_t& r1, uint32_t& r2, uint32_t& r3,
                                      uint32_t addr) {
    asm volatile("ldmatrix.sync.aligned.m8n8.x4.shared.b16 {%0,%1,%2,%3}, [%4];"
                 : "=r"(r0), "=r"(r1), "=r"(r2), "=r"(r3) : "r"(addr));
}
#define MMA(c, a0, a1, a2, a3, b0, b1) \
    asm volatile("mma.sync.aligned.m16n8k16.row.col.f32.bf16.bf16.f32 " \
        "{%0,%1,%2,%3}, {%4,%5,%6,%7}, {%8,%9}, {%0,%1,%2,%3};" \
        : "+f"((c)[0]), "+f"((c)[1]), "+f"((c)[2]), "+f"((c)[3]) \
        : "r"(a0), "r"(a1), "r"(a2), "r"(a3), "r"(b0), "r"(b1))

// ---------------- kernel A: Wh = h @ W (+ splits, s1/s2, zero reductions) ----------------
__global__ void __launch_bounds__(256) k_wh(const float* __restrict__ h,
                                            const float* __restrict__ W,
                                            const float* __restrict__ a) {
    __shared__ float hs[32][INF_];
    __shared__ float red[8][8][2];
    int i0 = blockIdx.x * 32;
    int tid = threadIdx.x;
    if (blockIdx.x < 48) {
        int z = blockIdx.x * 256 + tid;
        g_rs[z] = 0.f; g_cs[z] = 0.f;
    }
    if (blockIdx.x == 0 && tid == 0) g_badcnt = 0;
    const float4* hg = (const float4*)(h + (size_t)i0 * INF_);
    float4* hs4 = (float4*)hs;
#pragma unroll
    for (int k = 0; k < 8; k++) hs4[tid + 256 * k] = hg[tid + 256 * k];
    __syncthreads();
    int f = tid & 63, ir = tid >> 6, lane = tid & 31, wrp = tid >> 5;
    float acc[8];
#pragma unroll
    for (int r = 0; r < 8; r++) acc[r] = 0.f;
    for (int k = 0; k < INF_; k++) {
        float wk = W[k * FF + f];
#pragma unroll
        for (int r = 0; r < 8; r++) acc[r] += hs[ir * 8 + r][k] * wk;
    }
    float a1 = a[f], a2 = a[FF + f];
#pragma unroll
    for (int r = 0; r < 8; r++) {
        int i = i0 + ir * 8 + r;
        g_Wh[(size_t)i * FF + f] = acc[r];
        __nv_bfloat16 hb = __float2bfloat16(acc[r]);
        g_whT_h[(size_t)f * NN + i] = hb;
        g_whT_l[(size_t)f * NN + i] = __float2bfloat16(acc[r] - __bfloat162float(hb));
        float p1 = acc[r] * a1, p2 = acc[r] * a2;
#pragma unroll
        for (int o = 16; o > 0; o >>= 1) {
            p1 += __shfl_down_sync(0xffffffffu, p1, o);
            p2 += __shfl_down_sync(0xffffffffu, p2, o);
        }
        if (lane == 0) { red[wrp][r][0] = p1; red[wrp][r][1] = p2; }
    }
    __syncthreads();
    if (tid < 32) {
        int irr = tid >> 3, r = tid & 7;
        g_s1[i0 + irr * 8 + r] = red[2 * irr][r][0] + red[2 * irr + 1][r][0];
        g_s2[i0 + irr * 8 + r] = red[2 * irr][r][1] + red[2 * irr + 1][r][1];
    }
}

// ---------------- kernel S: bitonic sort s2 descending (4096 padded) ----------------
__global__ void __launch_bounds__(1024) k_sort() {
    __shared__ float key[4096];
    __shared__ int idx[4096];
    int tid = threadIdx.x;
#pragma unroll
    for (int t = tid; t < 4096; t += 1024) {
        key[t] = (t < NN) ? g_s2[t] : __int_as_float(0xff800000);  // -inf pad
        idx[t] = t;
    }
    for (int k = 2; k <= 4096; k <<= 1) {
        for (int j = k >> 1; j > 0; j >>= 1) {
            __syncthreads();
            for (int t = tid; t < 4096; t += 1024) {
                int ixj = t ^ j;
                if (ixj > t) {
                    bool up = (t & k) == 0;
                    float ka = key[t], kb = key[ixj];
                    // descending: larger first in "up" blocks
                    if (up ? (ka < kb) : (ka > kb)) {
                        key[t] = kb; key[ixj] = ka;
                        int ia = idx[t]; idx[t] = idx[ixj]; idx[ixj] = ia;
                    }
                }
            }
        }
    }
    __syncthreads();
    for (int t = tid; t < NN; t += 1024) { g_ss[t] = key[t]; g_perm[t] = idx[t]; }
}

// ---------------- kernel F: fused e + G1/G2 GEMMs + row/col sums ----------------
// grid (48, 4, 2): (i-tile 64 rows, p, j-half). 128 threads = 4 warps (16 rows each).
__global__ void __launch_bounds__(128, 3) k_fuse(const float* __restrict__ edge,
                                                 float* __restrict__ e_out) {
    __shared__ float edge_s[2][64][40];                 // 20.0 KB
    __shared__ __nv_bfloat16 b_hs[2][64][40];           // 10.0 KB
    __shared__ __nv_bfloat16 b_ls[2][64][40];           // 10.0 KB
    __shared__ float cs_s[JHALF];                       // 6 KB

    int tid = threadIdx.x, lane = tid & 31, w = tid >> 5;
    int p = blockIdx.y, i0 = blockIdx.x * 64;
    int half = blockIdx.z;
    int j0 = half * JHALF;

    for (int t = tid; t < JHALF; t += 128) cs_s[t] = 0.f;

    int g = lane >> 2, q = (lane & 3) * 2;
    int r0 = w * 16 + g, r1 = r0 + 8;
    float s1a = g_s1[i0 + r0], s1b = g_s1[i0 + r1];
    const float* egbase = edge + (size_t)p * NN * NN + (size_t)i0 * NN + j0;
    float* eobase = e_out + (size_t)p * NN * NN + (size_t)i0 * NN + j0;

    int brow = (lane & 7) + ((lane >> 1) & 8);
    int bk = ((lane >> 3) & 1) * 8;
    uint32_t eb0 = smem_u32(&edge_s[0][0][0]);
    uint32_t bhb0 = smem_u32(&b_hs[0][0][0]);
    uint32_t blb0 = smem_u32(&b_ls[0][0][0]);

#define STAGE(cc) do { \
    int st_ = (cc) & 1; \
    _Pragma("unroll") \
    for (int t = 0; t < 4; t++) { \
        int s = tid + t * 128;                  /* edge: 512 x 16B */ \
        int row = s >> 3, unit = s & 7; \
        cp_async16(eb0 + (uint32_t)(st_ * 10240 + (row * 40 + unit * 4) * 4), \
                   egbase + (size_t)row * NN + (cc) * FCH + unit * 4); \
    } \
    _Pragma("unroll") \
    for (int t = 0; t < 4; t++) { \
        int s = tid + t * 128;                  /* B: 2 x 256 x 16B */ \
        int m = s >> 8, sr = s & 255; \
        int fr = sr >> 2, unit = sr & 3; \
        uint32_t dst = (m ? blb0 : bhb0) + (uint32_t)(st_ * 5120 + fr * 80 + unit * 16); \
        const __nv_bfloat16* src = (m ? g_whT_l : g_whT_h) + (size_t)fr * NN + j0 + (cc) * FCH + unit * 8; \
        cp_async16(dst, src); \
    } \
    CP_COMMIT(); \
} while (0)

    float c1[8][4], c2[8][4];
#pragma unroll
    for (int n = 0; n < 8; n++)
#pragma unroll
        for (int r = 0; r < 4; r++) { c1[n][r] = 0.f; c2[n][r] = 0.f; }
    float rsum0 = 0.f, rsum1 = 0.f;

    STAGE(0);
    __syncthreads();   // cs_s zero visible

    for (int cc = 0; cc < NCH; cc++) {
        if (cc < NCH - 1) { STAGE(cc + 1); CP_WAIT(1); }
        else              { CP_WAIT(0); }
        __syncthreads();
        int st = cc & 1;
        uint32_t ebase = eb0 + (uint32_t)st * 10240;
        uint32_t bhbase = bhb0 + (uint32_t)st * 5120;
        uint32_t blbase = blb0 + (uint32_t)st * 5120;
        float csp[8];
#pragma unroll
        for (int k = 0; k < 8; k++) csp[k] = 0.f;

#pragma unroll
        for (int ks = 0; ks < 2; ks++) {
            int jb = cc * FCH + ks * 16;
            // edge from smem
            float2 ea00 = *(const float2*)((const char*)edge_s + (ebase - eb0) + (r0 * 40 + ks * 16 + q) * 4);
            float2 ea10 = *(const float2*)((const char*)edge_s + (ebase - eb0) + (r1 * 40 + ks * 16 + q) * 4);
            float2 ea01 = *(const float2*)((const char*)edge_s + (ebase - eb0) + (r0 * 40 + ks * 16 + q + 8) * 4);
            float2 ea11 = *(const float2*)((const char*)edge_s + (ebase - eb0) + (r1 * 40 + ks * 16 + q + 8) * 4);
            float2 s2A = *(const float2*)&g_s2[j0 + jb + q];
            float2 s2B = *(const float2*)&g_s2[j0 + jb + q + 8];

            float x, ev00x, ev00y, ev10x, ev10y, ev01x, ev01y, ev11x, ev11y;
            x = s1a + s2A.x; ev00x = (x > 0.f ? x : LALPHA * x) * ea00.x;
            x = s1a + s2A.y; ev00y = (x > 0.f ? x : LALPHA * x) * ea00.y;
            x = s1b + s2A.x; ev10x = (x > 0.f ? x : LALPHA * x) * ea10.x;
            x = s1b + s2A.y; ev10y = (x > 0.f ? x : LALPHA * x) * ea10.y;
            x = s1a + s2B.x; ev01x = (x > 0.f ? x : LALPHA * x) * ea01.x;
            x = s1a + s2B.y; ev01y = (x > 0.f ? x : LALPHA * x) * ea01.y;
            x = s1b + s2B.x; ev11x = (x > 0.f ? x : LALPHA * x) * ea11.x;
            x = s1b + s2B.y; ev11y = (x > 0.f ? x : LALPHA * x) * ea11.y;

            // bad-pair detection: edge==0 with threshold-mask positive
            if (ea00.x == 0.f && s2A.x > -s1a) { int sl = atomicAdd(&g_badcnt, 1); if (sl < MAXBAD) g_bad[sl] = (p << 24) | ((i0 + r0) << 12) | (j0 + jb + q); }
            if (ea00.y == 0.f && s2A.y > -s1a) { int sl = atomicAdd(&g_badcnt, 1); if (sl < MAXBAD) g_bad[sl] = (p << 24) | ((i0 + r0) << 12) | (j0 + jb + q + 1); }
            if (ea10.x == 0.f && s2A.x > -s1b) { int sl = atomicAdd(&g_badcnt, 1); if (sl < MAXBAD) g_bad[sl] = (p << 24) | ((i0 + r1) << 12) | (j0 + jb + q); }
            if (ea10.y == 0.f && s2A.y > -s1b) { int sl = atomicAdd(&g_badcnt, 1); if (sl < MAXBAD) g_bad[sl] = (p << 24) | ((i0 + r1) << 12) | (j0 + jb + q + 1); }
            if (ea01.x == 0.f && s2B.x > -s1a) { int sl = atomicAdd(&g_badcnt, 1); if (sl < MAXBAD) g_bad[sl] = (p << 24) | ((i0 + r0) << 12) | (j0 + jb + q + 8); }
            if (ea01.y == 0.f && s2B.y > -s1a) { int sl = atomicAdd(&g_badcnt, 1); if (sl < MAXBAD) g_bad[sl] = (p << 24) | ((i0 + r0) << 12) | (j0 + jb + q + 9); }
            if (ea11.x == 0.f && s2B.x > -s1b) { int sl = atomicAdd(&g_badcnt, 1); if (sl < MAXBAD) g_bad[sl] = (p << 24) | ((i0 + r1) << 12) | (j0 + jb + q + 8); }
            if (ea11.y == 0.f && s2B.y > -s1b) { int sl = atomicAdd(&g_badcnt, 1); if (sl < MAXBAD) g_bad[sl] = (p << 24) | ((i0 + r1) << 12) | (j0 + jb + q + 9); }

            // write e (streaming)
            __stcs((float2*)(eobase + (size_t)r0 * NN + jb + q),     make_float2(ev00x, ev00y));
            __stcs((float2*)(eobase + (size_t)r1 * NN + jb + q),     make_float2(ev10x, ev10y));
            __stcs((float2*)(eobase + (size_t)r0 * NN + jb + q + 8), make_float2(ev01x, ev01y));
            __stcs((float2*)(eobase + (size_t)r1 * NN + jb + q + 8), make_float2(ev11x, ev11y));

            // sums
            rsum0 += (ev00x + ev00y) + (ev01x + ev01y);
            rsum1 += (ev10x + ev10y) + (ev11x + ev11y);
            csp[ks * 4 + 0] += ev00x + ev10x;
            csp[ks * 4 + 1] += ev00y + ev10y;
            csp[ks * 4 + 2] += ev01x + ev11x;
            csp[ks * 4 + 3] += ev01y + ev11y;

            // A fragments: pos (bf16 hi only) and neg (hi+lo)
            float p00x = fmaxf(ev00x, 0.f), p00y = fmaxf(ev00y, 0.f);
            float p10x = fmaxf(ev10x, 0.f), p10y = fmaxf(ev10y, 0.f);
            float p01x = fmaxf(ev01x, 0.f), p01y = fmaxf(ev01y, 0.f);
            float p11x = fmaxf(ev11x, 0.f), p11y = fmaxf(ev11y, 0.f);
            float n00x = fminf(ev00x, 0.f), n00y = fminf(ev00y, 0.f);
            float n10x = fminf(ev10x, 0.f), n10y = fminf(ev10y, 0.f);
            float n01x = fminf(ev01x, 0.f), n01y = fminf(ev01y, 0.f);
            float n11x = fminf(ev11x, 0.f), n11y = fminf(ev11y, 0.f);
            uint32_t ap0, ap1, ap2, ap3, ah0, ah1, ah2, ah3, al0, al1, al2, al3;
            asm("cvt.rn.bf16x2.f32 %0, %1, %2;" : "=r"(ap0) : "f"(p00y), "f"(p00x));
            asm("cvt.rn.bf16x2.f32 %0, %1, %2;" : "=r"(ap1) : "f"(p10y), "f"(p10x));
            asm("cvt.rn.bf16x2.f32 %0, %1, %2;" : "=r"(ap2) : "f"(p01y), "f"(p01x));
            asm("cvt.rn.bf16x2.f32 %0, %1, %2;" : "=r"(ap3) : "f"(p11y), "f"(p11x));
            asm("cvt.rn.bf16x2.f32 %0, %1, %2;" : "=r"(ah0) : "f"(n00y), "f"(n00x));
            asm("cvt.rn.bf16x2.f32 %0, %1, %2;" : "=r"(ah1) : "f"(n10y), "f"(n10x));
            asm("cvt.rn.bf16x2.f32 %0, %1, %2;" : "=r"(ah2) : "f"(n01y), "f"(n01x));
            asm("cvt.rn.bf16x2.f32 %0, %1, %2;" : "=r"(ah3) : "f"(n11y), "f"(n11x));
            float q00x = n00x - __uint_as_float(ah0 << 16);
            float q00y = n00y - __uint_as_float(ah0 & 0xffff0000u);
            float q10x = n10x - __uint_as_float(ah1 << 16);
            float q10y = n10y - __uint_as_float(ah1 & 0xffff0000u);
            float q01x = n01x - __uint_as_float(ah2 << 16);
            float q01y = n01y - __uint_as_float(ah2 & 0xffff0000u);
            float q11x = n11x - __uint_as_float(ah3 << 16);
            float q11y = n11y - __uint_as_float(ah3 & 0xffff0000u);
            asm("cvt.rn.bf16x2.f32 %0, %1, %2;" : "=r"(al0) : "f"(q00y), "f"(q00x));
            asm("cvt.rn.bf16x2.f32 %0, %1, %2;" : "=r"(al1) : "f"(q10y), "f"(q10x));
            asm("cvt.rn.bf16x2.f32 %0, %1, %2;" : "=r"(al2) : "f"(q01y), "f"(q01x));
            asm("cvt.rn.bf16x2.f32 %0, %1, %2;" : "=r"(al3) : "f"(q11y), "f"(q11x));

            uint32_t lof = (uint32_t)(brow * 80 + (ks * 16 + bk) * 2);
#pragma unroll
            for (int np = 0; np < 4; np++) {
                uint32_t off = lof + np * 1280;
                uint32_t bh0, bh1, bh2, bh3, bl0, bl1, bl2, bl3;
                ldsm4(bh0, bh1, bh2, bh3, bhbase + off);
                ldsm4(bl0, bl1, bl2, bl3, blbase + off);
                MMA(c1[2 * np],     ap0, ap1, ap2, ap3, bh0, bh1);
                MMA(c1[2 * np + 1], ap0, ap1, ap2, ap3, bh2, bh3);
                MMA(c2[2 * np],     ah0, ah1, ah2, ah3, bh0, bh1);
                MMA(c2[2 * np],     al0, al1, al2, al3, bh0, bh1);
                MMA(c2[2 * np],     ah0, ah1, ah2, ah3, bl0, bl1);
                MMA(c2[2 * np + 1], ah0, ah1, ah2, ah3, bh2, bh3);
                MMA(c2[2 * np + 1], al0, al1, al2, al3, bh2, bh3);
                MMA(c2[2 * np + 1], ah0, ah1, ah2, ah3, bl2, bl3);
            }
        }
        // col partials -> smem (reduce across 8 row-groups)
#pragma unroll
        for (int k = 0; k < 8; k++) {
            csp[k] += __shfl_down_sync(0xffffffffu, csp[k], 4);
            csp[k] += __shfl_down_sync(0xffffffffu, csp[k], 8);
            csp[k] += __shfl_down_sync(0xffffffffu, csp[k], 16);
        }
        if (lane < 4) {
#pragma unroll
            for (int k = 0; k < 8; k++) {
                int kt = k >> 2, wh = k & 3;
                int col = cc * FCH + kt * 16 + (wh < 2 ? q + wh : q + 6 + wh);  // q+8, q+9
                atomicAdd(&cs_s[col], csp[k]);
            }
        }
        __syncthreads();
    }

    // row sums -> global
    rsum0 += __shfl_down_sync(0xffffffffu, rsum0, 1);
    rsum0 += __shfl_down_sync(0xffffffffu, rsum0, 2);
    rsum1 += __shfl_down_sync(0xffffffffu, rsum1, 1);
    rsum1 += __shfl_down_sync(0xffffffffu, rsum1, 2);
    if ((lane & 3) == 0) {
        atomicAdd(&g_rs[p * NN + i0 + r0], rsum0);
        atomicAdd(&g_rs[p * NN + i0 + r1], rsum1);
    }
    // col sums -> global
    for (int t = tid; t < JHALF; t += 128)
        atomicAdd(&g_cs[p * NN + j0 + t], cs_s[t]);

    // store G partials
    size_t gb = ((size_t)(half * PP + p) * NN + i0) * FF;
#pragma unroll
    for (int nt = 0; nt < 8; nt++) {
        int col = nt * 8 + q;
        *(float2*)(g_G1 + gb + (size_t)r0 * FF + col) = make_float2(c1[nt][0], c1[nt][1]);
        *(float2*)(g_G1 + gb + (size_t)r1 * FF + col) = make_float2(c1[nt][2], c1[nt][3]);
        *(float2*)(g_G2 + gb + (size_t)r0 * FF + col) = make_float2(c2[nt][0], c2[nt][1]);
        *(float2*)(g_G2 + gb + (size_t)r1 * FF + col) = make_float2(c2[nt][2], c2[nt][3]);
    }
#undef STAGE
}

// ---------------- kernel D: scalars + folded u/v ----------------
__global__ void k_scal() {
    int p = blockIdx.x;
    int tid = threadIdx.x;
    __shared__ float smx[256], ssm[256];
    __shared__ float lambS, invrS, invlS;
    float mx = -1e30f, sm = 0.f;
    for (int k = tid; k < NN; k += 256) {
        float rv = g_rs[p * NN + k];
        float cv = g_cs[p * NN + k];
        mx = fmaxf(mx, fmaxf(rv, cv));
        sm += rv;
    }
    smx[tid] = mx; ssm[tid] = sm;
    __syncthreads();
    for (int s = 128; s > 0; s >>= 1) {
        if (tid < s) { smx[tid] = fmaxf(smx[tid], smx[tid + s]); ssm[tid] += ssm[tid + s]; }
        __syncthreads();
    }
    if (tid == 0) {
        float lamb = smx[0];
        float r = (float)NN * lamb - ssm[0];
        lambS = lamb;
        invrS = 1.f / r;
        invlS = 1.f / lamb;     // analytic: tt.sum(axis=0)[0] == lamb
        g_par[p * 2] = invlS;
    }
    __syncthreads();
    float lamb = lambS, ir = invrS, il = invlS;
    for (int k = tid; k < NN; k += 256) {
        g_u[p * NN + k] = (lamb - g_rs[p * NN + k]) * ir;
        g_v[p * NN + k] = (lamb - g_cs[p * NN + k]) * il;
    }
}

// ---------------- kernel P1: per-chunk exclusive prefix of v_j*Wh[j,:] (sorted order) ----------------
__global__ void __launch_bounds__(64) k_pref1() {
    int b = blockIdx.x, p = blockIdx.y, f = threadIdx.x;
    int base = b * CHW;
    float run = 0.f;
    int jj = g_perm[base];
    float wv = g_Wh[(size_t)jj * FF + f];
    float vv = g_v[p * NN + jj];
    for (int t = 0; t < CHW; t++) {
        g_local[((size_t)p * NN + base + t) * FF + f] = run;
        float term = vv * wv;
        if (t < CHW - 1) {
            int jn = g_perm[base + t + 1];
            wv = g_Wh[(size_t)jn * FF + f];
            vv = g_v[p * NN + jn];
        }
        run += term;
    }
    g_tot[((size_t)p * 64 + b) * FF + f] = run;
}

// ---------------- kernel P2: scan chunk totals ----------------
__global__ void __launch_bounds__(64) k_pref2() {
    int p = blockIdx.x, f = threadIdx.x;
    float run = 0.f;
    for (int c0 = 0; c0 < 64; c0 += 8) {
        float tv[8];
#pragma unroll
        for (int k = 0; k < 8; k++) tv[k] = g_tot[((size_t)p * 64 + c0 + k) * FF + f];
#pragma unroll
        for (int k = 0; k < 8; k++) {
            g_offs[((size_t)p * 65 + c0 + k) * FF + f] = run;
            run += tv[k];
        }
    }
    g_offs[((size_t)p * 65 + 64) * FF + f] = run;
}

// ---------------- kernel O: combine + S2 + corrections + elu ----------------
__global__ void __launch_bounds__(256) k_out(float* __restrict__ out0) {
    int i = blockIdx.x * 4 + (threadIdx.x >> 6);
    int f = threadIdx.x & 63;
    int badn = g_badcnt; if (badn > MAXBAD) badn = MAXBAD;
    float s1i = g_s1[i];
    float t = -s1i;
    // rank: count of s2_j > t (desc sorted)
    int lo = 0, hi = NN;
    while (lo < hi) {
        int mid = (lo + hi) >> 1;
        if (__ldg(&g_ss[mid]) > t) lo = mid + 1; else hi = mid;
    }
    int r = lo;
#pragma unroll
    for (int p = 0; p < PP; p++) {
        float S2f;
        if (r >= NN) S2f = g_offs[((size_t)p * 65 + 64) * FF + f];
        else S2f = g_offs[((size_t)p * 65 + (r / CHW)) * FF + f]
                 + g_local[((size_t)p * NN + r) * FF + f];
        float u = g_u[p * NN + i];
        float invl = g_par[p * 2];
        size_t gi = ((size_t)p * NN + i) * FF + f;
        float g1 = g_G1[gi] + g_G1[(size_t)PP * NN * FF + gi];
        float g2 = g_G2[gi] + g_G2[(size_t)PP * NN * FF + gi];
        float hv = fmaf(invl, g1, g2) + u * S2f;
        for (int b = 0; b < badn; b++) {
            unsigned e = g_bad[b];
            if ((int)(e >> 24) == p && (int)((e >> 12) & 4095) == i) {
                int j = e & 4095;
                hv -= u * g_v[p * NN + j] * g_Wh[(size_t)j * FF + f];
            }
        }
        out0[(size_t)i * (PP * FF) + p * FF + f] = hv > 0.f ? hv : expm1f(hv);
    }
}

// ---------------- launch ----------------
extern "C" void kernel_launch(void* const* d_in, const int* in_sizes, int n_in,
                              void* d_out, int out_size) {
    const float* h    = (const float*)d_in[0];
    const float* edge = (const float*)d_in[1];
    const float* W    = (const float*)d_in[2];
    const float* a    = (const float*)d_in[3];
    float* out = (float*)d_out;

    float* e_dst;
    long long need = (long long)NN * PP * FF + (long long)PP * NN * NN;
    if ((long long)out_size >= need) {
        e_dst = out + (size_t)NN * PP * FF;
    } else {
        void* pe = nullptr;
        cudaGetSymbolAddress(&pe, g_e);
        e_dst = (float*)pe;
    }

    k_wh<<<NN / 32, 256>>>(h, W, a);
    k_sort<<<1, 1024>>>();
    k_fuse<<<dim3(NN / 64, PP, 2), 128>>>(edge, e_dst);
    k_scal<<<PP, 256>>>();
    k_pref1<<<dim3(64, PP), 64>>>();
    k_pref2<<<PP, 64>>>();
    k_out<<<NN / 4, 256>>>(out);
}

// round 8
// speedup vs baseline: 1.1880x; 1.1880x over previous
#include <cuda_runtime.h>
#include <cuda_bf16.h>
#include <cstdint>

#define NN 3072
#define PP 4
#define FF 64
#define INF_ 256
#define LALPHA 0.2f
#define JHALF 1536
#define FCH 32
#define NCH (JHALF / FCH)      // 48
#define CHW 48                 // prefix chunk width (3072 = 64*48)

// ---------------- device scratch ----------------
__device__ float g_Wh[NN * FF];
__device__ float g_s1[NN];
__device__ float g_s2[NN];
__device__ float g_rs[PP * NN];
__device__ float g_cs[PP * NN];
__device__ float g_u[PP * NN];               // (lamb - rs) * inv_r
__device__ float g_v[PP * NN];               // (lamb - cs) * inv_l
__device__ float g_par[PP * 2];              // [p*2] = inv_l
__device__ __nv_bfloat16 g_whT_h[FF * NN];   // Wh^T bf16 hi [f][j]
__device__ __nv_bfloat16 g_whT_l[FF * NN];   // residual lo
__device__ float g_ss[NN];                   // s2 sorted desc
__device__ int   g_perm[NN];                 // sort permutation
__device__ float g_local[PP * NN * FF];      // in-chunk exclusive prefix of v*Wh
__device__ float g_tot[PP * 64 * FF];        // chunk totals
__device__ float g_offs[PP * 65 * FF];       // scanned chunk offsets
__device__ float g_G1[2 * PP * NN * FF];     // pos GEMM partials (per j-half)
__device__ float g_G2[2 * PP * NN * FF];     // neg GEMM partials
__device__ float g_e[(size_t)PP * NN * NN];  // fallback e storage

__device__ __forceinline__ uint32_t smem_u32(const void* p) {
    uint32_t a;
    asm("{ .reg .u64 t; cvta.to.shared.u64 t, %1; cvt.u32.u64 %0, t; }" : "=r"(a) : "l"(p));
    return a;
}
__device__ __forceinline__ void cp_async16(uint32_t dst, const void* src) {
    asm volatile("cp.async.cg.shared.global [%0], [%1], 16;" :: "r"(dst), "l"(src) : "memory");
}
#define CP_COMMIT() asm volatile("cp.async.commit_group;" ::: "memory")
#define CP_WAIT(N)  asm volatile("cp.async.wait_group %0;" :: "n"(N) : "memory")
__device__ __forceinline__ void ldsm4(uint32_t& r0, uint32_t& r1, uint32_t& r2, uint32_t& r3,
                                      uint32_t addr) {
    asm volatile("ldmatrix.sync.aligned.m8n8.x4.shared.b16 {%0,%1,%2,%3}, [%4];"
                 : "=r"(r0), "=r"(r1), "=r"(r2), "=r"(r3) : "r"(addr));
}
#define MMA(c, a0, a1, a2, a3, b0, b1) \
    asm volatile("mma.sync.aligned.m16n8k16.row.col.f32.bf16.bf16.f32 " \
        "{%0,%1,%2,%3}, {%4,%5,%6,%7}, {%8,%9}, {%0,%1,%2,%3};" \
        : "+f"((c)[0]), "+f"((c)[1]), "+f"((c)[2]), "+f"((c)[3]) \
        : "r"(a0), "r"(a1), "r"(a2), "r"(a3), "r"(b0), "r"(b1))

// ---------------- kernel A: Wh = h @ W (+ splits, s1/s2, zero reductions) ----------------
__global__ void __launch_bounds__(256) k_wh(const float* __restrict__ h,
                                            const float* __restrict__ W,
                                            const float* __restrict__ a) {
    __shared__ float hs[32][INF_];
    __shared__ float red[8][8][2];
    int i0 = blockIdx.x * 32;
    int tid = threadIdx.x;
    if (blockIdx.x < 48) {
        int z = blockIdx.x * 256 + tid;
        g_rs[z] = 0.f; g_cs[z] = 0.f;
    }
    const float4* hg = (const float4*)(h + (size_t)i0 * INF_);
    float4* hs4 = (float4*)hs;
#pragma unroll
    for (int k = 0; k < 8; k++) hs4[tid + 256 * k] = hg[tid + 256 * k];
    __syncthreads();
    int f = tid & 63, ir = tid >> 6, lane = tid & 31, wrp = tid >> 5;
    float acc[8];
#pragma unroll
    for (int r = 0; r < 8; r++) acc[r] = 0.f;
    for (int k = 0; k < INF_; k++) {
        float wk = W[k * FF + f];
#pragma unroll
        for (int r = 0; r < 8; r++) acc[r] += hs[ir * 8 + r][k] * wk;
    }
    float a1 = a[f], a2 = a[FF + f];
#pragma unroll
    for (int r = 0; r < 8; r++) {
        int i = i0 + ir * 8 + r;
        g_Wh[(size_t)i * FF + f] = acc[r];
        __nv_bfloat16 hb = __float2bfloat16(acc[r]);
        g_whT_h[(size_t)f * NN + i] = hb;
        g_whT_l[(size_t)f * NN + i] = __float2bfloat16(acc[r] - __bfloat162float(hb));
        float p1 = acc[r] * a1, p2 = acc[r] * a2;
#pragma unroll
        for (int o = 16; o > 0; o >>= 1) {
            p1 += __shfl_down_sync(0xffffffffu, p1, o);
            p2 += __shfl_down_sync(0xffffffffu, p2, o);
        }
        if (lane == 0) { red[wrp][r][0] = p1; red[wrp][r][1] = p2; }
    }
    __syncthreads();
    if (tid < 32) {
        int irr = tid >> 3, r = tid & 7;
        g_s1[i0 + irr * 8 + r] = red[2 * irr][r][0] + red[2 * irr + 1][r][0];
        g_s2[i0 + irr * 8 + r] = red[2 * irr][r][1] + red[2 * irr + 1][r][1];
    }
}

// ---------------- kernel F: fused e + G1/G2 GEMMs + row/col sums ----------------
// grid (48, 4, 2): (i-tile 64 rows, p, j-half). 128 threads = 4 warps (16 rows each).
__global__ void __launch_bounds__(128, 3) k_fuse(const float* __restrict__ edge,
                                                 float* __restrict__ e_out) {
    __shared__ float edge_s[2][64][40];                 // 20.0 KB
    __shared__ __nv_bfloat16 b_hs[2][64][40];           // 10.0 KB
    __shared__ __nv_bfloat16 b_ls[2][64][40];           // 10.0 KB
    __shared__ float cs_s[JHALF];                       // 6 KB

    int tid = threadIdx.x, lane = tid & 31, w = tid >> 5;
    int p = blockIdx.y, i0 = blockIdx.x * 64;
    int half = blockIdx.z;
    int j0 = half * JHALF;

    for (int t = tid; t < JHALF; t += 128) cs_s[t] = 0.f;

    int g = lane >> 2, q = (lane & 3) * 2;
    int r0 = w * 16 + g, r1 = r0 + 8;
    float s1a = g_s1[i0 + r0], s1b = g_s1[i0 + r1];
    const float* egbase = edge + (size_t)p * NN * NN + (size_t)i0 * NN + j0;
    float* eobase = e_out + (size_t)p * NN * NN + (size_t)i0 * NN + j0;

    int brow = (lane & 7) + ((lane >> 1) & 8);
    int bk = ((lane >> 3) & 1) * 8;
    uint32_t eb0 = smem_u32(&edge_s[0][0][0]);
    uint32_t bhb0 = smem_u32(&b_hs[0][0][0]);
    uint32_t blb0 = smem_u32(&b_ls[0][0][0]);

#define STAGE(cc) do { \
    int st_ = (cc) & 1; \
    _Pragma("unroll") \
    for (int t = 0; t < 4; t++) { \
        int s = tid + t * 128;                  /* edge: 512 x 16B */ \
        int row = s >> 3, unit = s & 7; \
        cp_async16(eb0 + (uint32_t)(st_ * 10240 + (row * 40 + unit * 4) * 4), \
                   egbase + (size_t)row * NN + (cc) * FCH + unit * 4); \
    } \
    _Pragma("unroll") \
    for (int t = 0; t < 4; t++) { \
        int s = tid + t * 128;                  /* B: 2 x 256 x 16B */ \
        int m = s >> 8, sr = s & 255; \
        int fr = sr >> 2, unit = sr & 3; \
        uint32_t dst = (m ? blb0 : bhb0) + (uint32_t)(st_ * 5120 + fr * 80 + unit * 16); \
        const __nv_bfloat16* src = (m ? g_whT_l : g_whT_h) + (size_t)fr * NN + j0 + (cc) * FCH + unit * 8; \
        cp_async16(dst, src); \
    } \
    CP_COMMIT(); \
} while (0)

    float c1[8][4], c2[8][4];
#pragma unroll
    for (int n = 0; n < 8; n++)
#pragma unroll
        for (int r = 0; r < 4; r++) { c1[n][r] = 0.f; c2[n][r] = 0.f; }
    float rsum0 = 0.f, rsum1 = 0.f;

    STAGE(0);
    __syncthreads();   // cs_s zero visible

    for (int cc = 0; cc < NCH; cc++) {
        if (cc < NCH - 1) { STAGE(cc + 1); CP_WAIT(1); }
        else              { CP_WAIT(0); }
        __syncthreads();
        int st = cc & 1;
        uint32_t ebase = eb0 + (uint32_t)st * 10240;
        uint32_t bhbase = bhb0 + (uint32_t)st * 5120;
        uint32_t blbase = blb0 + (uint32_t)st * 5120;
        float csp[8];
#pragma unroll
        for (int k = 0; k < 8; k++) csp[k] = 0.f;

#pragma unroll
        for (int ks = 0; ks < 2; ks++) {
            int jb = cc * FCH + ks * 16;
            // edge from smem
            float2 ea00 = *(const float2*)((const char*)edge_s + (ebase - eb0) + (r0 * 40 + ks * 16 + q) * 4);
            float2 ea10 = *(const float2*)((const char*)edge_s + (ebase - eb0) + (r1 * 40 + ks * 16 + q) * 4);
            float2 ea01 = *(const float2*)((const char*)edge_s + (ebase - eb0) + (r0 * 40 + ks * 16 + q + 8) * 4);
            float2 ea11 = *(const float2*)((const char*)edge_s + (ebase - eb0) + (r1 * 40 + ks * 16 + q + 8) * 4);
            float2 s2A = *(const float2*)&g_s2[j0 + jb + q];
            float2 s2B = *(const float2*)&g_s2[j0 + jb + q + 8];

            float x, ev00x, ev00y, ev10x, ev10y, ev01x, ev01y, ev11x, ev11y;
            x = s1a + s2A.x; ev00x = (x > 0.f ? x : LALPHA * x) * ea00.x;
            x = s1a + s2A.y; ev00y = (x > 0.f ? x : LALPHA * x) * ea00.y;
            x = s1b + s2A.x; ev10x = (x > 0.f ? x : LALPHA * x) * ea10.x;
            x = s1b + s2A.y; ev10y = (x > 0.f ? x : LALPHA * x) * ea10.y;
            x = s1a + s2B.x; ev01x = (x > 0.f ? x : LALPHA * x) * ea01.x;
            x = s1a + s2B.y; ev01y = (x > 0.f ? x : LALPHA * x) * ea01.y;
            x = s1b + s2B.x; ev11x = (x > 0.f ? x : LALPHA * x) * ea11.x;
            x = s1b + s2B.y; ev11y = (x > 0.f ? x : LALPHA * x) * ea11.y;

            // write e (streaming)
            __stcs((float2*)(eobase + (size_t)r0 * NN + jb + q),     make_float2(ev00x, ev00y));
            __stcs((float2*)(eobase + (size_t)r1 * NN + jb + q),     make_float2(ev10x, ev10y));
            __stcs((float2*)(eobase + (size_t)r0 * NN + jb + q + 8), make_float2(ev01x, ev01y));
            __stcs((float2*)(eobase + (size_t)r1 * NN + jb + q + 8), make_float2(ev11x, ev11y));

            // sums
            rsum0 += (ev00x + ev00y) + (ev01x + ev01y);
            rsum1 += (ev10x + ev10y) + (ev11x + ev11y);
            csp[ks * 4 + 0] += ev00x + ev10x;
            csp[ks * 4 + 1] += ev00y + ev10y;
            csp[ks * 4 + 2] += ev01x + ev11x;
            csp[ks * 4 + 3] += ev01y + ev11y;

            // A fragments: pos (bf16 hi) and neg (bf16 hi) -- no residuals
            uint32_t ap0, ap1, ap2, ap3, ah0, ah1, ah2, ah3;
            asm("cvt.rn.bf16x2.f32 %0, %1, %2;" : "=r"(ap0) : "f"(fmaxf(ev00y, 0.f)), "f"(fmaxf(ev00x, 0.f)));
            asm("cvt.rn.bf16x2.f32 %0, %1, %2;" : "=r"(ap1) : "f"(fmaxf(ev10y, 0.f)), "f"(fmaxf(ev10x, 0.f)));
            asm("cvt.rn.bf16x2.f32 %0, %1, %2;" : "=r"(ap2) : "f"(fmaxf(ev01y, 0.f)), "f"(fmaxf(ev01x, 0.f)));
            asm("cvt.rn.bf16x2.f32 %0, %1, %2;" : "=r"(ap3) : "f"(fmaxf(ev11y, 0.f)), "f"(fmaxf(ev11x, 0.f)));
            asm("cvt.rn.bf16x2.f32 %0, %1, %2;" : "=r"(ah0) : "f"(fminf(ev00y, 0.f)), "f"(fminf(ev00x, 0.f)));
            asm("cvt.rn.bf16x2.f32 %0, %1, %2;" : "=r"(ah1) : "f"(fminf(ev10y, 0.f)), "f"(fminf(ev10x, 0.f)));
            asm("cvt.rn.bf16x2.f32 %0, %1, %2;" : "=r"(ah2) : "f"(fminf(ev01y, 0.f)), "f"(fminf(ev01x, 0.f)));
            asm("cvt.rn.bf16x2.f32 %0, %1, %2;" : "=r"(ah3) : "f"(fminf(ev11y, 0.f)), "f"(fminf(ev11x, 0.f)));

            uint32_t lof = (uint32_t)(brow * 80 + (ks * 16 + bk) * 2);
#pragma unroll
            for (int np = 0; np < 4; np++) {
                uint32_t off = lof + np * 1280;
                uint32_t bh0, bh1, bh2, bh3, bl0, bl1, bl2, bl3;
                ldsm4(bh0, bh1, bh2, bh3, bhbase + off);
                ldsm4(bl0, bl1, bl2, bl3, blbase + off);
                MMA(c1[2 * np],     ap0, ap1, ap2, ap3, bh0, bh1);
                MMA(c1[2 * np + 1], ap0, ap1, ap2, ap3, bh2, bh3);
                MMA(c2[2 * np],     ah0, ah1, ah2, ah3, bh0, bh1);
                MMA(c2[2 * np],     ah0, ah1, ah2, ah3, bl0, bl1);
                MMA(c2[2 * np + 1], ah0, ah1, ah2, ah3, bh2, bh3);
                MMA(c2[2 * np + 1], ah0, ah1, ah2, ah3, bl2, bl3);
            }
        }
        // col partials -> smem (reduce across 8 row-groups)
#pragma unroll
        for (int k = 0; k < 8; k++) {
            csp[k] += __shfl_down_sync(0xffffffffu, csp[k], 4);
            csp[k] += __shfl_down_sync(0xffffffffu, csp[k], 8);
            csp[k] += __shfl_down_sync(0xffffffffu, csp[k], 16);
        }
        if (lane < 4) {
#pragma unroll
            for (int k = 0; k < 8; k++) {
                int kt = k >> 2, wh = k & 3;
                int col = cc * FCH + kt * 16 + (wh < 2 ? q + wh : q + 6 + wh);  // q+8, q+9
                atomicAdd(&cs_s[col], csp[k]);
            }
        }
        __syncthreads();
    }

    // row sums -> global
    rsum0 += __shfl_down_sync(0xffffffffu, rsum0, 1);
    rsum0 += __shfl_down_sync(0xffffffffu, rsum0, 2);
    rsum1 += __shfl_down_sync(0xffffffffu, rsum1, 1);
    rsum1 += __shfl_down_sync(0xffffffffu, rsum1, 2);
    if ((lane & 3) == 0) {
        atomicAdd(&g_rs[p * NN + i0 + r0], rsum0);
        atomicAdd(&g_rs[p * NN + i0 + r1], rsum1);
    }
    // col sums -> global
    for (int t = tid; t < JHALF; t += 128)
        atomicAdd(&g_cs[p * NN + j0 + t], cs_s[t]);

    // store G partials
    size_t gb = ((size_t)(half * PP + p) * NN + i0) * FF;
#pragma unroll
    for (int nt = 0; nt < 8; nt++) {
        int col = nt * 8 + q;
        *(float2*)(g_G1 + gb + (size_t)r0 * FF + col) = make_float2(c1[nt][0], c1[nt][1]);
        *(float2*)(g_G1 + gb + (size_t)r1 * FF + col) = make_float2(c1[nt][2], c1[nt][3]);
        *(float2*)(g_G2 + gb + (size_t)r0 * FF + col) = make_float2(c2[nt][0], c2[nt][1]);
        *(float2*)(g_G2 + gb + (size_t)r1 * FF + col) = make_float2(c2[nt][2], c2[nt][3]);
    }
#undef STAGE
}

// ---------------- kernel D: scalars + u/v (blocks 0-3)  |  bitonic sort (block 4) ----------------
__global__ void __launch_bounds__(1024) k_scal_sort() {
    __shared__ float keyS[4096];
    __shared__ int   idxS[4096];
    int tid = threadIdx.x;
    if (blockIdx.x < 4) {
        int p = blockIdx.x;
        float* smx = keyS;                 // reuse smem
        float* ssm = (float*)idxS;
        __shared__ float lambS, invrS, invlS;
        float mx = -1e30f, sm = 0.f;
        for (int k = tid; k < NN; k += 1024) {
            float rv = g_rs[p * NN + k];
            float cv = g_cs[p * NN + k];
            mx = fmaxf(mx, fmaxf(rv, cv));
            sm += rv;
        }
        smx[tid] = mx; ssm[tid] = sm;
        __syncthreads();
        for (int s = 512; s > 0; s >>= 1) {
            if (tid < s) { smx[tid] = fmaxf(smx[tid], smx[tid + s]); ssm[tid] += ssm[tid + s]; }
            __syncthreads();
        }
        if (tid == 0) {
            float lamb = smx[0];
            float r = (float)NN * lamb - ssm[0];
            lambS = lamb; invrS = 1.f / r; invlS = 1.f / lamb;
            g_par[p * 2] = invlS;
        }
        __syncthreads();
        float lamb = lambS, ir = invrS, il = invlS;
        for (int k = tid; k < NN; k += 1024) {
            g_u[p * NN + k] = (lamb - g_rs[p * NN + k]) * ir;
            g_v[p * NN + k] = (lamb - g_cs[p * NN + k]) * il;
        }
    } else {
        // bitonic sort s2 descending, 4096 padded
#pragma unroll
        for (int t = tid; t < 4096; t += 1024) {
            keyS[t] = (t < NN) ? g_s2[t] : __int_as_float(0xff800000);
            idxS[t] = t;
        }
        for (int k = 2; k <= 4096; k <<= 1) {
            for (int j = k >> 1; j > 0; j >>= 1) {
                __syncthreads();
                for (int t = tid; t < 4096; t += 1024) {
                    int ixj = t ^ j;
                    if (ixj > t) {
                        bool up = (t & k) == 0;
                        float ka = keyS[t], kb = keyS[ixj];
                        if (up ? (ka < kb) : (ka > kb)) {
                            keyS[t] = kb; keyS[ixj] = ka;
                            int ia = idxS[t]; idxS[t] = idxS[ixj]; idxS[ixj] = ia;
                        }
                    }
                }
            }
        }
        __syncthreads();
        for (int t = tid; t < NN; t += 1024) { g_ss[t] = keyS[t]; g_perm[t] = idxS[t]; }
    }
}

// ---------------- kernel P1: per-chunk exclusive prefix of v_j*Wh[j,:] (sorted order) ----------------
__global__ void __launch_bounds__(64) k_pref1() {
    __shared__ int   psh[CHW];
    __shared__ float vsh[CHW];
    int b = blockIdx.x, p = blockIdx.y, f = threadIdx.x;
    int base = b * CHW;
    if (f < CHW) {
        int jj = g_perm[base + f];
        psh[f] = jj;
        vsh[f] = g_v[p * NN + jj];
    }
    __syncthreads();
    float run = 0.f;
    float wbuf[4];
#pragma unroll
    for (int k = 0; k < 4; k++) wbuf[k] = g_Wh[(size_t)psh[k] * FF + f];
    for (int t0 = 0; t0 < CHW; t0 += 4) {
        float wn[4] = {0.f, 0.f, 0.f, 0.f};
        if (t0 + 4 < CHW) {
#pragma unroll
            for (int k = 0; k < 4; k++) wn[k] = g_Wh[(size_t)psh[t0 + 4 + k] * FF + f];
        }
#pragma unroll
        for (int k = 0; k < 4; k++) {
            g_local[((size_t)p * NN + base + t0 + k) * FF + f] = run;
            run += vsh[t0 + k] * wbuf[k];
        }
#pragma unroll
        for (int k = 0; k < 4; k++) wbuf[k] = wn[k];
    }
    g_tot[((size_t)p * 64 + b) * FF + f] = run;
}

// ---------------- kernel P2: scan chunk totals ----------------
__global__ void __launch_bounds__(64) k_pref2() {
    int p = blockIdx.x, f = threadIdx.x;
    float run = 0.f;
    for (int c0 = 0; c0 < 64; c0 += 8) {
        float tv[8];
#pragma unroll
        for (int k = 0; k < 8; k++) tv[k] = g_tot[((size_t)p * 64 + c0 + k) * FF + f];
#pragma unroll
        for (int k = 0; k < 8; k++) {
            g_offs[((size_t)p * 65 + c0 + k) * FF + f] = run;
            run += tv[k];
        }
    }
    g_offs[((size_t)p * 65 + 64) * FF + f] = run;
}

// ---------------- kernel O: combine + S2 + elu ----------------
__global__ void __launch_bounds__(256) k_out(float* __restrict__ out0) {
    int i = blockIdx.x * 4 + (threadIdx.x >> 6);
    int f = threadIdx.x & 63;
    float s1i = g_s1[i];
    float t = -s1i;
    int lo = 0, hi = NN;
    while (lo < hi) {
        int mid = (lo + hi) >> 1;
        if (__ldg(&g_ss[mid]) > t) lo = mid + 1; else hi = mid;
    }
    int r = lo;
#pragma unroll
    for (int p = 0; p < PP; p++) {
        float S2f;
        if (r >= NN) S2f = g_offs[((size_t)p * 65 + 64) * FF + f];
        else S2f = g_offs[((size_t)p * 65 + (r / CHW)) * FF + f]
                 + g_local[((size_t)p * NN + r) * FF + f];
        float u = g_u[p * NN + i];
        float invl = g_par[p * 2];
        size_t gi = ((size_t)p * NN + i) * FF + f;
        float g1 = g_G1[gi] + g_G1[(size_t)PP * NN * FF + gi];
        float g2 = g_G2[gi] + g_G2[(size_t)PP * NN * FF + gi];
        float hv = fmaf(invl, g1, g2) + u * S2f;
        out0[(size_t)i * (PP * FF) + p * FF + f] = hv > 0.f ? hv : expm1f(hv);
    }
}

// ---------------- launch ----------------
extern "C" void kernel_launch(void* const* d_in, const int* in_sizes, int n_in,
                              void* d_out, int out_size) {
    const float* h    = (const float*)d_in[0];
    const float* edge = (const float*)d_in[1];
    const float* W    = (const float*)d_in[2];
    const float* a    = (const float*)d_in[3];
    float* out = (float*)d_out;

    float* e_dst;
    long long need = (long long)NN * PP * FF + (long long)PP * NN * NN;
    if ((long long)out_size >= need) {
        e_dst = out + (size_t)NN * PP * FF;
    } else {
        void* pe = nullptr;
        cudaGetSymbolAddress(&pe, g_e);
        e_dst = (float*)pe;
    }

    k_wh<<<NN / 32, 256>>>(h, W, a);
    k_fuse<<<dim3(NN / 64, PP, 2), 128>>>(edge, e_dst);
    k_scal_sort<<<5, 1024>>>();
    k_pref1<<<dim3(64, PP), 64>>>();
    k_pref2<<<PP, 64>>>();
    k_out<<<NN / 4, 256>>>(out);
}

// round 9
// speedup vs baseline: 1.6205x; 1.3640x over previous
#include <cuda_runtime.h>
#include <cuda_bf16.h>
#include <cstdint>

#define NN 3072
#define PP 4
#define FF 64
#define INF_ 256
#define LALPHA 0.2f
#define NSPLIT 3
#define JT3 (NN / NSPLIT)          // 1024
#define NCHUNK (JT3 / 64)          // 16

// ---------------- device scratch ----------------
__device__ float g_Wh[NN * FF];
__device__ float g_s1[NN];
__device__ float g_s2[NN];
__device__ float g_rs[PP * NN];
__device__ float g_cs[PP * NN];
__device__ float g_u[PP * NN];               // (lamb - rs) * inv_r
__device__ float g_v[PP * NN];               // (lamb - cs) * inv_l
__device__ float g_par[PP * 2];              // [p*2] = inv_l
__device__ __nv_bfloat16 g_whT_h[FF * NN];   // Wh^T bf16 hi [f][j]
__device__ __nv_bfloat16 g_whT_l[FF * NN];   // residual lo
__device__ float g_part[NSPLIT][NN * PP * FF];
__device__ float g_e[(size_t)PP * NN * NN];  // fallback e storage

__device__ __forceinline__ uint32_t smem_u32(const void* p) {
    uint32_t a;
    asm("{ .reg .u64 t; cvta.to.shared.u64 t, %1; cvt.u32.u64 %0, t; }" : "=r"(a) : "l"(p));
    return a;
}
__device__ __forceinline__ uint32_t swz(uint32_t o) { return o ^ ((o >> 3) & 0x70); }
__device__ __forceinline__ void cp_async16(uint32_t dst, const void* src) {
    asm volatile("cp.async.cg.shared.global [%0], [%1], 16;" :: "r"(dst), "l"(src) : "memory");
}
#define CP_COMMIT() asm volatile("cp.async.commit_group;" ::: "memory")
#define CP_WAIT(N)  asm volatile("cp.async.wait_group %0;" :: "n"(N) : "memory")
__device__ __forceinline__ void ldsm4(uint32_t& r0, uint32_t& r1, uint32_t& r2, uint32_t& r3,
                                      uint32_t addr) {
    asm volatile("ldmatrix.sync.aligned.m8n8.x4.shared.b16 {%0,%1,%2,%3}, [%4];"
                 : "=r"(r0), "=r"(r1), "=r"(r2), "=r"(r3) : "r"(addr));
}
#define MMA(c, a0, a1, a2, a3, b0, b1) \
    asm volatile("mma.sync.aligned.m16n8k16.row.col.f32.bf16.bf16.f32 " \
        "{%0,%1,%2,%3}, {%4,%5,%6,%7}, {%8,%9}, {%0,%1,%2,%3};" \
        : "+f"((c)[0]), "+f"((c)[1]), "+f"((c)[2]), "+f"((c)[3]) \
        : "r"(a0), "r"(a1), "r"(a2), "r"(a3), "r"(b0), "r"(b1))

// ---------------- kernel A: Wh = h @ W (+ splits, s1/s2, zero reductions) ----------------
__global__ void __launch_bounds__(256) k_wh(const float* __restrict__ h,
                                            const float* __restrict__ W,
                                            const float* __restrict__ a) {
    __shared__ float hs[32][INF_];
    __shared__ float red[8][8][2];
    int i0 = blockIdx.x * 32;
    int tid = threadIdx.x;
    if (blockIdx.x < 48) {
        int z = blockIdx.x * 256 + tid;
        g_rs[z] = 0.f; g_cs[z] = 0.f;
    }
    const float4* hg = (const float4*)(h + (size_t)i0 * INF_);
    float4* hs4 = (float4*)hs;
#pragma unroll
    for (int k = 0; k < 8; k++) hs4[tid + 256 * k] = hg[tid + 256 * k];
    __syncthreads();
    int f = tid & 63, ir = tid >> 6, lane = tid & 31, wrp = tid >> 5;
    float acc[8];
#pragma unroll
    for (int r = 0; r < 8; r++) acc[r] = 0.f;
    for (int k = 0; k < INF_; k++) {
        float wk = W[k * FF + f];
#pragma unroll
        for (int r = 0; r < 8; r++) acc[r] += hs[ir * 8 + r][k] * wk;
    }
    float a1 = a[f], a2 = a[FF + f];
#pragma unroll
    for (int r = 0; r < 8; r++) {
        int i = i0 + ir * 8 + r;
        g_Wh[(size_t)i * FF + f] = acc[r];
        __nv_bfloat16 hb = __float2bfloat16(acc[r]);
        g_whT_h[(size_t)f * NN + i] = hb;
        g_whT_l[(size_t)f * NN + i] = __float2bfloat16(acc[r] - __bfloat162float(hb));
        float p1 = acc[r] * a1, p2 = acc[r] * a2;
#pragma unroll
        for (int o = 16; o > 0; o >>= 1) {
            p1 += __shfl_down_sync(0xffffffffu, p1, o);
            p2 += __shfl_down_sync(0xffffffffu, p2, o);
        }
        if (lane == 0) { red[wrp][r][0] = p1; red[wrp][r][1] = p2; }
    }
    __syncthreads();
    if (tid < 32) {
        int irr = tid >> 3, r = tid & 7;
        g_s1[i0 + irr * 8 + r] = red[2 * irr][r][0] + red[2 * irr + 1][r][0];
        g_s2[i0 + irr * 8 + r] = red[2 * irr][r][1] + red[2 * irr + 1][r][1];
    }
}

// ---------------- kernel C: e + row/col sums ----------------
__global__ void __launch_bounds__(256) k_pass1(const float* __restrict__ edge,
                                               float* __restrict__ e_out) {
    int p = blockIdx.y;
    int i0 = blockIdx.x * 16;
    int tid = threadIdx.x;
    const float4* s2v = (const float4*)g_s2;
    float4 s2r[3];
#pragma unroll
    for (int k = 0; k < 3; k++) s2r[k] = s2v[tid + 256 * k];
    float4 ca[3];
#pragma unroll
    for (int k = 0; k < 3; k++) ca[k] = make_float4(0.f, 0.f, 0.f, 0.f);

    const float4* eg = (const float4*)(edge + (size_t)p * NN * NN);
    float4* eo = (float4*)(e_out + (size_t)p * NN * NN);

    for (int r = 0; r < 16; r++) {
        int i = i0 + r;
        float s1i = g_s1[i];
        size_t rb = (size_t)i * (NN / 4);
        float rp = 0.f;
#pragma unroll
        for (int k = 0; k < 3; k++) {
            float4 ea = eg[rb + tid + 256 * k];
            float4 s2q = s2r[k];
            float4 ev; float x;
            x = s1i + s2q.x; x = x > 0.f ? x : LALPHA * x; ev.x = x * ea.x;
            x = s1i + s2q.y; x = x > 0.f ? x : LALPHA * x; ev.y = x * ea.y;
            x = s1i + s2q.z; x = x > 0.f ? x : LALPHA * x; ev.z = x * ea.z;
            x = s1i + s2q.w; x = x > 0.f ? x : LALPHA * x; ev.w = x * ea.w;
            eo[rb + tid + 256 * k] = ev;
            rp += (ev.x + ev.y) + (ev.z + ev.w);
            ca[k].x += ev.x; ca[k].y += ev.y; ca[k].z += ev.z; ca[k].w += ev.w;
        }
#pragma unroll
        for (int o = 16; o > 0; o >>= 1) rp += __shfl_down_sync(0xffffffffu, rp, o);
        if ((tid & 31) == 0) atomicAdd(&g_rs[p * NN + i], rp);
    }
#pragma unroll
    for (int k = 0; k < 3; k++) {
        int j = (tid + 256 * k) * 4;
        atomicAdd(&g_cs[p * NN + j + 0], ca[k].x);
        atomicAdd(&g_cs[p * NN + j + 1], ca[k].y);
        atomicAdd(&g_cs[p * NN + j + 2], ca[k].z);
        atomicAdd(&g_cs[p * NN + j + 3], ca[k].w);
    }
}

// ---------------- kernel D: scalars + folded u/v (1024 threads) ----------------
__global__ void __launch_bounds__(1024) k_scal() {
    int p = blockIdx.x;
    int tid = threadIdx.x;
    __shared__ float smx[1024], ssm[1024];
    __shared__ float lambS, invrS, invlS;
    float mx = -1e30f, sm = 0.f;
#pragma unroll
    for (int k = tid; k < NN; k += 1024) {
        float rv = g_rs[p * NN + k];
        float cv = g_cs[p * NN + k];
        mx = fmaxf(mx, fmaxf(rv, cv));
        sm += rv;
    }
    smx[tid] = mx; ssm[tid] = sm;
    __syncthreads();
    for (int s = 512; s > 0; s >>= 1) {
        if (tid < s) { smx[tid] = fmaxf(smx[tid], smx[tid + s]); ssm[tid] += ssm[tid + s]; }
        __syncthreads();
    }
    if (tid == 0) {
        float lamb = smx[0];
        float r = (float)NN * lamb - ssm[0];
        lambS = lamb; invrS = 1.f / r; invlS = 1.f / lamb;  // analytic: col-normalizer == lamb
        g_par[p * 2] = invlS;
    }
    __syncthreads();
    float lamb = lambS, ir = invrS, il = invlS;
#pragma unroll
    for (int k = tid; k < NN; k += 1024) {
        g_u[p * NN + k] = (lamb - g_rs[p * NN + k]) * ir;
        g_v[p * NN + k] = (lamb - g_cs[p * NN + k]) * il;
    }
}

// ---------------- kernel E: pipelined smem-B mma.sync GEMM, j-split x3, reverse order ----------------
// grid (48, 4, 3), 128 threads = 4 warps; warp w -> rows [w*16, w*16+16)
__global__ void __launch_bounds__(128) k_pass2p(const float* __restrict__ e_in,
                                                float* __restrict__ part) {
    __shared__ __align__(16) __nv_bfloat16 bs[2][2][64 * 64];  // 32KB
    __shared__ float v_s[JT3];                                 // 4KB

    int tid = threadIdx.x, lane = tid & 31, w = tid >> 5;
    int p = blockIdx.y, i0 = blockIdx.x * 64;
    int third = blockIdx.z;
    int j0 = third * JT3;
    float inv_l = g_par[p * 2];

    int g = lane >> 2, q = (lane & 3) * 2;
    int row0 = i0 + w * 16 + g;
    float u0 = g_u[p * NN + row0];
    float u1 = g_u[p * NN + row0 + 8];
    const float* ep0 = e_in + (size_t)p * NN * NN + (size_t)row0 * NN + j0 + q;
    const float* ep1 = ep0 + (size_t)8 * NN;

    int brow = (lane & 7) + ((lane >> 1) & 8);
    int bk = ((lane >> 3) & 1) * 8;
    uint32_t bs_base0 = smem_u32(&bs[0][0][0]);

#define STAGE_B(cc) do { \
    uint32_t dstb = bs_base0 + (((cc) & 1) ? 16384u : 0u); \
    _Pragma("unroll") \
    for (int t = 0; t < 4; t++) { \
        int s = tid + t * 128; \
        int fr = s >> 3, col = s & 7; \
        uint32_t o = swz((uint32_t)(fr * 128 + col * 16)); \
        cp_async16(dstb + o,        g_whT_h + (size_t)fr * NN + j0 + (cc) * 64 + col * 8); \
        cp_async16(dstb + 8192 + o, g_whT_l + (size_t)fr * NN + j0 + (cc) * 64 + col * 8); \
    } \
    CP_COMMIT(); \
} while (0)

#define LOAD_E(dst, cc) do { \
    _Pragma("unroll") \
    for (int ks = 0; ks < 4; ks++) { \
        int kb = (cc) * 64 + ks * 16; \
        dst[ks][0] = __ldcs((const float2*)(ep0 + kb)); \
        dst[ks][1] = __ldcs((const float2*)(ep1 + kb)); \
        dst[ks][2] = __ldcs((const float2*)(ep0 + kb + 8)); \
        dst[ks][3] = __ldcs((const float2*)(ep1 + kb + 8)); \
    } \
} while (0)

    STAGE_B(NCHUNK - 1);
    {   // stage v for this j-third
        const float4* vg = (const float4*)(g_v + p * NN + j0);
        float4* vs4 = (float4*)v_s;
#pragma unroll
        for (int k = 0; k < 2; k++) vs4[tid + 128 * k] = vg[tid + 128 * k];
    }

    float2 ecur[4][4], enxt[4][4];
    LOAD_E(ecur, NCHUNK - 1);

    float cacc[8][4];
#pragma unroll
    for (int n = 0; n < 8; n++)
#pragma unroll
        for (int r = 0; r < 4; r++) cacc[n][r] = 0.f;

    // reverse order: read e newest-first to catch pass1's tail in L2
    for (int ch = NCHUNK - 1; ch >= 0; ch--) {
        if (ch > 0) { STAGE_B(ch - 1); CP_WAIT(1); }
        else        { CP_WAIT(0); }
        __syncthreads();
        if (ch > 0) LOAD_E(enxt, ch - 1);

        uint32_t sbase = bs_base0 + ((ch & 1) ? 16384u : 0u);
#pragma unroll
        for (int ks = 0; ks < 4; ks++) {
            int kb = ch * 64 + ks * 16;
            float2 e00 = ecur[ks][0], e10 = ecur[ks][1];
            float2 e01 = ecur[ks][2], e11 = ecur[ks][3];
            float2 vA = *(const float2*)&v_s[kb + q];
            float2 vB = *(const float2*)&v_s[kb + q + 8];
            float a00 = e00.x > 0.f ? fmaf(u0, vA.x, e00.x * inv_l) : e00.x;
            float a01 = e00.y > 0.f ? fmaf(u0, vA.y, e00.y * inv_l) : e00.y;
            float a10 = e10.x > 0.f ? fmaf(u1, vA.x, e10.x * inv_l) : e10.x;
            float a11 = e10.y > 0.f ? fmaf(u1, vA.y, e10.y * inv_l) : e10.y;
            float a02 = e01.x > 0.f ? fmaf(u0, vB.x, e01.x * inv_l) : e01.x;
            float a03 = e01.y > 0.f ? fmaf(u0, vB.y, e01.y * inv_l) : e01.y;
            float a12 = e11.x > 0.f ? fmaf(u1, vB.x, e11.x * inv_l) : e11.x;
            float a13 = e11.y > 0.f ? fmaf(u1, vB.y, e11.y * inv_l) : e11.y;
            uint32_t ah0, ah1, ah2, ah3, al0, al1, al2, al3;
            asm("cvt.rn.bf16x2.f32 %0, %1, %2;" : "=r"(ah0) : "f"(a01), "f"(a00));
            asm("cvt.rn.bf16x2.f32 %0, %1, %2;" : "=r"(ah1) : "f"(a11), "f"(a10));
            asm("cvt.rn.bf16x2.f32 %0, %1, %2;" : "=r"(ah2) : "f"(a03), "f"(a02));
            asm("cvt.rn.bf16x2.f32 %0, %1, %2;" : "=r"(ah3) : "f"(a13), "f"(a12));
            float r00 = a00 - __uint_as_float(ah0 << 16);
            float r01 = a01 - __uint_as_float(ah0 & 0xffff0000u);
            float r10 = a10 - __uint_as_float(ah1 << 16);
            float r11 = a11 - __uint_as_float(ah1 & 0xffff0000u);
            float r02 = a02 - __uint_as_float(ah2 << 16);
            float r03 = a03 - __uint_as_float(ah2 & 0xffff0000u);
            float r12 = a12 - __uint_as_float(ah3 << 16);
            float r13 = a13 - __uint_as_float(ah3 & 0xffff0000u);
            asm("cvt.rn.bf16x2.f32 %0, %1, %2;" : "=r"(al0) : "f"(r01), "f"(r00));
            asm("cvt.rn.bf16x2.f32 %0, %1, %2;" : "=r"(al1) : "f"(r11), "f"(r10));
            asm("cvt.rn.bf16x2.f32 %0, %1, %2;" : "=r"(al2) : "f"(r03), "f"(r02));
            asm("cvt.rn.bf16x2.f32 %0, %1, %2;" : "=r"(al3) : "f"(r13), "f"(r12));

            uint32_t lof = (uint32_t)(brow * 128 + (ks * 16 + bk) * 2);
#pragma unroll
            for (int np = 0; np < 4; np++) {
                uint32_t off = swz(lof + np * 2048);
                uint32_t bh0, bh1, bh2, bh3, bl0, bl1, bl2, bl3;
                ldsm4(bh0, bh1, bh2, bh3, sbase + off);
                ldsm4(bl0, bl1, bl2, bl3, sbase + 8192 + off);
                MMA(cacc[2 * np],     ah0, ah1, ah2, ah3, bh0, bh1);
                MMA(cacc[2 * np],     al0, al1, al2, al3, bh0, bh1);
                MMA(cacc[2 * np],     ah0, ah1, ah2, ah3, bl0, bl1);
                MMA(cacc[2 * np + 1], ah0, ah1, ah2, ah3, bh2, bh3);
                MMA(cacc[2 * np + 1], al0, al1, al2, al3, bh2, bh3);
                MMA(cacc[2 * np + 1], ah0, ah1, ah2, ah3, bl2, bl3);
            }
        }
        __syncthreads();
#pragma unroll
        for (int ks = 0; ks < 4; ks++)
#pragma unroll
            for (int t = 0; t < 4; t++) ecur[ks][t] = enxt[ks][t];
    }

    // ---- store partials ----
    float* o0 = part + (size_t)third * (NN * PP * FF)
              + (size_t)row0 * (PP * FF) + p * FF + q;
    float* o1 = o0 + (size_t)8 * (PP * FF);
#pragma unroll
    for (int n = 0; n < 8; n++) {
        *(float2*)(o0 + n * 8) = make_float2(cacc[n][0], cacc[n][1]);
        *(float2*)(o1 + n * 8) = make_float2(cacc[n][2], cacc[n][3]);
    }
#undef STAGE_B
#undef LOAD_E
}

// ---------------- kernel F: combine thirds + elu ----------------
__global__ void __launch_bounds__(256) k_elu(const float* __restrict__ part,
                                             float* __restrict__ out0) {
    int i = blockIdx.x * 256 + threadIdx.x;
    float4 a = ((const float4*)part)[i];
    float4 b = ((const float4*)(part + (size_t)NN * PP * FF))[i];
    float4 c = ((const float4*)(part + (size_t)2 * NN * PP * FF))[i];
    float4 v;
    v.x = a.x + b.x + c.x; v.y = a.y + b.y + c.y;
    v.z = a.z + b.z + c.z; v.w = a.w + b.w + c.w;
    v.x = v.x > 0.f ? v.x : expm1f(v.x);
    v.y = v.y > 0.f ? v.y : expm1f(v.y);
    v.z = v.z > 0.f ? v.z : expm1f(v.z);
    v.w = v.w > 0.f ? v.w : expm1f(v.w);
    ((float4*)out0)[i] = v;
}

// ---------------- launch ----------------
extern "C" void kernel_launch(void* const* d_in, const int* in_sizes, int n_in,
                              void* d_out, int out_size) {
    const float* h    = (const float*)d_in[0];
    const float* edge = (const float*)d_in[1];
    const float* W    = (const float*)d_in[2];
    const float* a    = (const float*)d_in[3];
    float* out = (float*)d_out;

    float* e_dst;
    long long need = (long long)NN * PP * FF + (long long)PP * NN * NN;
    if ((long long)out_size >= need) {
        e_dst = out + (size_t)NN * PP * FF;
    } else {
        void* pe = nullptr;
        cudaGetSymbolAddress(&pe, g_e);
        e_dst = (float*)pe;
    }
    void* ppart = nullptr;
    cudaGetSymbolAddress(&ppart, g_part);
    float* part = (float*)ppart;

    k_wh<<<NN / 32, 256>>>(h, W, a);
    k_pass1<<<dim3(NN / 16, PP), 256>>>(edge, e_dst);
    k_scal<<<PP, 1024>>>();
    k_pass2p<<<dim3(NN / 64, PP, NSPLIT), 128>>>(e_dst, part);
    k_elu<<<(NN * PP * FF / 4 + 255) / 256, 256>>>(part, out);
}

// round 10
// speedup vs baseline: 1.6830x; 1.0386x over previous
#include <cuda_runtime.h>
#include <cuda_bf16.h>
#include <cstdint>

#define NN 3072
#define PP 4
#define FF 64
#define INF_ 256
#define LALPHA 0.2f
#define NSPLIT 3
#define JT3 (NN / NSPLIT)          // 1024
#define NCHUNK (JT3 / 64)          // 16

// ---------------- device scratch ----------------
__device__ float g_Wh[NN * FF];
__device__ float g_s1[NN];
__device__ float g_s2[NN];
__device__ float g_rs[PP * NN];
__device__ float g_cs[PP * NN];
__device__ __nv_bfloat16 g_whT_h[FF * NN];   // Wh^T bf16 hi [f][j]
__device__ __nv_bfloat16 g_whT_l[FF * NN];   // residual lo
__device__ float g_part[NSPLIT][NN * PP * FF];
__device__ float g_e[(size_t)PP * NN * NN];  // fallback e storage

__device__ __forceinline__ uint32_t smem_u32(const void* p) {
    uint32_t a;
    asm("{ .reg .u64 t; cvta.to.shared.u64 t, %1; cvt.u32.u64 %0, t; }" : "=r"(a) : "l"(p));
    return a;
}
__device__ __forceinline__ uint32_t swz(uint32_t o) { return o ^ ((o >> 3) & 0x70); }
__device__ __forceinline__ void cp_async16(uint32_t dst, const void* src) {
    asm volatile("cp.async.cg.shared.global [%0], [%1], 16;" :: "r"(dst), "l"(src) : "memory");
}
#define CP_COMMIT() asm volatile("cp.async.commit_group;" ::: "memory")
#define CP_WAIT(N)  asm volatile("cp.async.wait_group %0;" :: "n"(N) : "memory")
__device__ __forceinline__ void ldsm4(uint32_t& r0, uint32_t& r1, uint32_t& r2, uint32_t& r3,
                                      uint32_t addr) {
    asm volatile("ldmatrix.sync.aligned.m8n8.x4.shared.b16 {%0,%1,%2,%3}, [%4];"
                 : "=r"(r0), "=r"(r1), "=r"(r2), "=r"(r3) : "r"(addr));
}
#define MMA(c, a0, a1, a2, a3, b0, b1) \
    asm volatile("mma.sync.aligned.m16n8k16.row.col.f32.bf16.bf16.f32 " \
        "{%0,%1,%2,%3}, {%4,%5,%6,%7}, {%8,%9}, {%0,%1,%2,%3};" \
        : "+f"((c)[0]), "+f"((c)[1]), "+f"((c)[2]), "+f"((c)[3]) \
        : "r"(a0), "r"(a1), "r"(a2), "r"(a3), "r"(b0), "r"(b1))

// ---------------- kernel A: Wh = h @ W (+ splits, s1/s2, zero reductions) ----------------
__global__ void __launch_bounds__(256) k_wh(const float* __restrict__ h,
                                            const float* __restrict__ W,
                                            const float* __restrict__ a) {
    __shared__ float hs[32][INF_];
    __shared__ float red[8][8][2];
    int i0 = blockIdx.x * 32;
    int tid = threadIdx.x;
    if (blockIdx.x < 48) {
        int z = blockIdx.x * 256 + tid;
        g_rs[z] = 0.f; g_cs[z] = 0.f;
    }
    const float4* hg = (const float4*)(h + (size_t)i0 * INF_);
    float4* hs4 = (float4*)hs;
#pragma unroll
    for (int k = 0; k < 8; k++) hs4[tid + 256 * k] = hg[tid + 256 * k];
    __syncthreads();
    int f = tid & 63, ir = tid >> 6, lane = tid & 31, wrp = tid >> 5;
    float acc[8];
#pragma unroll
    for (int r = 0; r < 8; r++) acc[r] = 0.f;
    for (int k = 0; k < INF_; k++) {
        float wk = W[k * FF + f];
#pragma unroll
        for (int r = 0; r < 8; r++) acc[r] += hs[ir * 8 + r][k] * wk;
    }
    float a1 = a[f], a2 = a[FF + f];
#pragma unroll
    for (int r = 0; r < 8; r++) {
        int i = i0 + ir * 8 + r;
        g_Wh[(size_t)i * FF + f] = acc[r];
        __nv_bfloat16 hb = __float2bfloat16(acc[r]);
        g_whT_h[(size_t)f * NN + i] = hb;
        g_whT_l[(size_t)f * NN + i] = __float2bfloat16(acc[r] - __bfloat162float(hb));
        float p1 = acc[r] * a1, p2 = acc[r] * a2;
#pragma unroll
        for (int o = 16; o > 0; o >>= 1) {
            p1 += __shfl_down_sync(0xffffffffu, p1, o);
            p2 += __shfl_down_sync(0xffffffffu, p2, o);
        }
        if (lane == 0) { red[wrp][r][0] = p1; red[wrp][r][1] = p2; }
    }
    __syncthreads();
    if (tid < 32) {
        int irr = tid >> 3, r = tid & 7;
        g_s1[i0 + irr * 8 + r] = red[2 * irr][r][0] + red[2 * irr + 1][r][0];
        g_s2[i0 + irr * 8 + r] = red[2 * irr][r][1] + red[2 * irr + 1][r][1];
    }
}

// ---------------- kernel C: e + row/col sums ----------------
__global__ void __launch_bounds__(256) k_pass1(const float* __restrict__ edge,
                                               float* __restrict__ e_out) {
    int p = blockIdx.y;
    int i0 = blockIdx.x * 16;
    int tid = threadIdx.x;
    const float4* s2v = (const float4*)g_s2;
    float4 s2r[3];
#pragma unroll
    for (int k = 0; k < 3; k++) s2r[k] = s2v[tid + 256 * k];
    float4 ca[3];
#pragma unroll
    for (int k = 0; k < 3; k++) ca[k] = make_float4(0.f, 0.f, 0.f, 0.f);

    const float4* eg = (const float4*)(edge + (size_t)p * NN * NN);
    float4* eo = (float4*)(e_out + (size_t)p * NN * NN);

    for (int r = 0; r < 16; r++) {
        int i = i0 + r;
        float s1i = g_s1[i];
        size_t rb = (size_t)i * (NN / 4);
        float rp = 0.f;
#pragma unroll
        for (int k = 0; k < 3; k++) {
            float4 ea = eg[rb + tid + 256 * k];
            float4 s2q = s2r[k];
            float4 ev; float x;
            x = s1i + s2q.x; x = x > 0.f ? x : LALPHA * x; ev.x = x * ea.x;
            x = s1i + s2q.y; x = x > 0.f ? x : LALPHA * x; ev.y = x * ea.y;
            x = s1i + s2q.z; x = x > 0.f ? x : LALPHA * x; ev.z = x * ea.z;
            x = s1i + s2q.w; x = x > 0.f ? x : LALPHA * x; ev.w = x * ea.w;
            eo[rb + tid + 256 * k] = ev;
            rp += (ev.x + ev.y) + (ev.z + ev.w);
            ca[k].x += ev.x; ca[k].y += ev.y; ca[k].z += ev.z; ca[k].w += ev.w;
        }
#pragma unroll
        for (int o = 16; o > 0; o >>= 1) rp += __shfl_down_sync(0xffffffffu, rp, o);
        if ((tid & 31) == 0) atomicAdd(&g_rs[p * NN + i], rp);
    }
#pragma unroll
    for (int k = 0; k < 3; k++) {
        int j = (tid + 256 * k) * 4;
        atomicAdd(&g_cs[p * NN + j + 0], ca[k].x);
        atomicAdd(&g_cs[p * NN + j + 1], ca[k].y);
        atomicAdd(&g_cs[p * NN + j + 2], ca[k].z);
        atomicAdd(&g_cs[p * NN + j + 3], ca[k].w);
    }
}

// ---------------- kernel E: pipelined smem-B mma.sync GEMM, j-split x3 ----------------
// grid (48, 4, 3), 128 threads = 4 warps; per-block inline scalar reduction (lamb/inv_r/inv_l)
__global__ void __launch_bounds__(128, 4) k_pass2p(const float* __restrict__ e_in,
                                                   float* __restrict__ part) {
    __shared__ __align__(16) __nv_bfloat16 bs[2][2][64 * 64];  // 32KB
    __shared__ float v_s[JT3];                                 // 4KB
    __shared__ float red1[128], red2[128];

    int tid = threadIdx.x, lane = tid & 31, w = tid >> 5;
    int p = blockIdx.y, i0 = blockIdx.x * 64;
    int third = blockIdx.z;
    int j0 = third * JT3;

    int g = lane >> 2, q = (lane & 3) * 2;
    int row0 = i0 + w * 16 + g;

    int brow = (lane & 7) + ((lane >> 1) & 8);
    int bk = ((lane >> 3) & 1) * 8;
    uint32_t bs_base0 = smem_u32(&bs[0][0][0]);

#define STAGE_B(cc) do { \
    uint32_t dstb = bs_base0 + (((cc) & 1) ? 16384u : 0u); \
    _Pragma("unroll") \
    for (int t = 0; t < 4; t++) { \
        int s = tid + t * 128; \
        int fr = s >> 3, col = s & 7; \
        uint32_t o = swz((uint32_t)(fr * 128 + col * 16)); \
        cp_async16(dstb + o,        g_whT_h + (size_t)fr * NN + j0 + (cc) * 64 + col * 8); \
        cp_async16(dstb + 8192 + o, g_whT_l + (size_t)fr * NN + j0 + (cc) * 64 + col * 8); \
    } \
    CP_COMMIT(); \
} while (0)

#define LOAD_E(dst, cc) do { \
    _Pragma("unroll") \
    for (int ks = 0; ks < 4; ks++) { \
        int kb = (cc) * 64 + ks * 16; \
        dst[ks][0] = __ldcs((const float2*)(ep0 + kb)); \
        dst[ks][1] = __ldcs((const float2*)(ep1 + kb)); \
        dst[ks][2] = __ldcs((const float2*)(ep0 + kb + 8)); \
        dst[ks][3] = __ldcs((const float2*)(ep1 + kb + 8)); \
    } \
} while (0)

    STAGE_B(NCHUNK - 1);   // overlap the B prefetch with the scalar reduction below

    // ---- inline scalar reduction: lamb = max(rs,cs), r = N*lamb - sum(rs) ----
    {
        float mx = -1e30f, sm = 0.f;
#pragma unroll
        for (int k = tid; k < NN; k += 128) {
            float rv = g_rs[p * NN + k];
            float cv = g_cs[p * NN + k];
            mx = fmaxf(mx, fmaxf(rv, cv));
            sm += rv;
        }
        red1[tid] = mx; red2[tid] = sm;
        __syncthreads();
        for (int s = 64; s > 0; s >>= 1) {
            if (tid < s) { red1[tid] = fmaxf(red1[tid], red1[tid + s]); red2[tid] += red2[tid + s]; }
            __syncthreads();
        }
    }
    float lamb = red1[0];
    float inv_r = 1.f / ((float)NN * lamb - red2[0]);
    float inv_l = 1.f / lamb;   // analytic: col-normalizer == lamb

    float u0 = (lamb - g_rs[p * NN + row0]) * inv_r;
    float u1 = (lamb - g_rs[p * NN + row0 + 8]) * inv_r;
    const float* ep0 = e_in + (size_t)p * NN * NN + (size_t)row0 * NN + j0 + q;
    const float* ep1 = ep0 + (size_t)8 * NN;

    // stage v for this j-third: v = (lamb - cs) * inv_l
#pragma unroll
    for (int t = tid; t < JT3; t += 128)
        v_s[t] = (lamb - g_cs[p * NN + j0 + t]) * inv_l;

    float2 ecur[4][4], enxt[4][4];
    LOAD_E(ecur, NCHUNK - 1);

    float cacc[8][4];
#pragma unroll
    for (int n = 0; n < 8; n++)
#pragma unroll
        for (int r = 0; r < 4; r++) cacc[n][r] = 0.f;

    // reverse order: read e newest-first to catch pass1's tail in L2
    for (int ch = NCHUNK - 1; ch >= 0; ch--) {
        if (ch > 0) { STAGE_B(ch - 1); LOAD_E(enxt, ch - 1); CP_WAIT(1); }
        else        { CP_WAIT(0); }
        __syncthreads();

        uint32_t sbase = bs_base0 + ((ch & 1) ? 16384u : 0u);
#pragma unroll
        for (int ks = 0; ks < 4; ks++) {
            int kb = ch * 64 + ks * 16;
            float2 e00 = ecur[ks][0], e10 = ecur[ks][1];
            float2 e01 = ecur[ks][2], e11 = ecur[ks][3];
            float2 vA = *(const float2*)&v_s[kb + q];
            float2 vB = *(const float2*)&v_s[kb + q + 8];
            float a00 = e00.x > 0.f ? fmaf(u0, vA.x, e00.x * inv_l) : e00.x;
            float a01 = e00.y > 0.f ? fmaf(u0, vA.y, e00.y * inv_l) : e00.y;
            float a10 = e10.x > 0.f ? fmaf(u1, vA.x, e10.x * inv_l) : e10.x;
            float a11 = e10.y > 0.f ? fmaf(u1, vA.y, e10.y * inv_l) : e10.y;
            float a02 = e01.x > 0.f ? fmaf(u0, vB.x, e01.x * inv_l) : e01.x;
            float a03 = e01.y > 0.f ? fmaf(u0, vB.y, e01.y * inv_l) : e01.y;
            float a12 = e11.x > 0.f ? fmaf(u1, vB.x, e11.x * inv_l) : e11.x;
            float a13 = e11.y > 0.f ? fmaf(u1, vB.y, e11.y * inv_l) : e11.y;
            uint32_t ah0, ah1, ah2, ah3, al0, al1, al2, al3;
            asm("cvt.rn.bf16x2.f32 %0, %1, %2;" : "=r"(ah0) : "f"(a01), "f"(a00));
            asm("cvt.rn.bf16x2.f32 %0, %1, %2;" : "=r"(ah1) : "f"(a11), "f"(a10));
            asm("cvt.rn.bf16x2.f32 %0, %1, %2;" : "=r"(ah2) : "f"(a03), "f"(a02));
            asm("cvt.rn.bf16x2.f32 %0, %1, %2;" : "=r"(ah3) : "f"(a13), "f"(a12));
            float r00 = a00 - __uint_as_float(ah0 << 16);
            float r01 = a01 - __uint_as_float(ah0 & 0xffff0000u);
            float r10 = a10 - __uint_as_float(ah1 << 16);
            float r11 = a11 - __uint_as_float(ah1 & 0xffff0000u);
            float r02 = a02 - __uint_as_float(ah2 << 16);
            float r03 = a03 - __uint_as_float(ah2 & 0xffff0000u);
            float r12 = a12 - __uint_as_float(ah3 << 16);
            float r13 = a13 - __uint_as_float(ah3 & 0xffff0000u);
            asm("cvt.rn.bf16x2.f32 %0, %1, %2;" : "=r"(al0) : "f"(r01), "f"(r00));
            asm("cvt.rn.bf16x2.f32 %0, %1, %2;" : "=r"(al1) : "f"(r11), "f"(r10));
            asm("cvt.rn.bf16x2.f32 %0, %1, %2;" : "=r"(al2) : "f"(r03), "f"(r02));
            asm("cvt.rn.bf16x2.f32 %0, %1, %2;" : "=r"(al3) : "f"(r13), "f"(r12));

            uint32_t lof = (uint32_t)(brow * 128 + (ks * 16 + bk) * 2);
#pragma unroll
            for (int np = 0; np < 4; np++) {
                uint32_t off = swz(lof + np * 2048);
                uint32_t bh0, bh1, bh2, bh3, bl0, bl1, bl2, bl3;
                ldsm4(bh0, bh1, bh2, bh3, sbase + off);
                ldsm4(bl0, bl1, bl2, bl3, sbase + 8192 + off);
                MMA(cacc[2 * np],     ah0, ah1, ah2, ah3, bh0, bh1);
                MMA(cacc[2 * np],     al0, al1, al2, al3, bh0, bh1);
                MMA(cacc[2 * np],     ah0, ah1, ah2, ah3, bl0, bl1);
                MMA(cacc[2 * np + 1], ah0, ah1, ah2, ah3, bh2, bh3);
                MMA(cacc[2 * np + 1], al0, al1, al2, al3, bh2, bh3);
                MMA(cacc[2 * np + 1], ah0, ah1, ah2, ah3, bl2, bl3);
            }
        }
        __syncthreads();
#pragma unroll
        for (int ks = 0; ks < 4; ks++)
#pragma unroll
            for (int t = 0; t < 4; t++) ecur[ks][t] = enxt[ks][t];
    }

    // ---- store partials ----
    float* o0 = part + (size_t)third * (NN * PP * FF)
              + (size_t)row0 * (PP * FF) + p * FF + q;
    float* o1 = o0 + (size_t)8 * (PP * FF);
#pragma unroll
    for (int n = 0; n < 8; n++) {
        *(float2*)(o0 + n * 8) = make_float2(cacc[n][0], cacc[n][1]);
        *(float2*)(o1 + n * 8) = make_float2(cacc[n][2], cacc[n][3]);
    }
#undef STAGE_B
#undef LOAD_E
}

// ---------------- kernel F: combine thirds + elu ----------------
__global__ void __launch_bounds__(256) k_elu(const float* __restrict__ part,
                                             float* __restrict__ out0) {
    int i = blockIdx.x * 256 + threadIdx.x;
    float4 a = ((const float4*)part)[i];
    float4 b = ((const float4*)(part + (size_t)NN * PP * FF))[i];
    float4 c = ((const float4*)(part + (size_t)2 * NN * PP * FF))[i];
    float4 v;
    v.x = a.x + b.x + c.x; v.y = a.y + b.y + c.y;
    v.z = a.z + b.z + c.z; v.w = a.w + b.w + c.w;
    v.x = v.x > 0.f ? v.x : expm1f(v.x);
    v.y = v.y > 0.f ? v.y : expm1f(v.y);
    v.z = v.z > 0.f ? v.z : expm1f(v.z);
    v.w = v.w > 0.f ? v.w : expm1f(v.w);
    ((float4*)out0)[i] = v;
}

// ---------------- launch ----------------
extern "C" void kernel_launch(void* const* d_in, const int* in_sizes, int n_in,
                              void* d_out, int out_size) {
    const float* h    = (const float*)d_in[0];
    const float* edge = (const float*)d_in[1];
    const float* W    = (const float*)d_in[2];
    const float* a    = (const float*)d_in[3];
    float* out = (float*)d_out;

    float* e_dst;
    long long need = (long long)NN * PP * FF + (long long)PP * NN * NN;
    if ((long long)out_size >= need) {
        e_dst = out + (size_t)NN * PP * FF;
    } else {
        void* pe = nullptr;
        cudaGetSymbolAddress(&pe, g_e);
        e_dst = (float*)pe;
    }
    void* ppart = nullptr;
    cudaGetSymbolAddress(&ppart, g_part);
    float* part = (float*)ppart;

    k_wh<<<NN / 32, 256>>>(h, W, a);
    k_pass1<<<dim3(NN / 16, PP), 256>>>(edge, e_dst);
    k_pass2p<<<dim3(NN / 64, PP, NSPLIT), 128>>>(e_dst, part);
    k_elu<<<(NN * PP * FF / 4 + 255) / 256, 256>>>(part, out);
}

// round 11
// speedup vs baseline: 1.7984x; 1.0686x over previous
#include <cuda_runtime.h>
#include <cuda_bf16.h>
#include <cstdint>

#define NN 3072
#define PP 4
#define FF 64
#define INF_ 256
#define LALPHA 0.2f
#define NSPLIT 3
#define JT3 (NN / NSPLIT)          // 1024
#define NCHUNK (JT3 / 64)          // 16

// dynamic smem layout for k_pass2p
#define SM_BS   0                  // bf16 bs[2][2][64*64]   : 32768 B
#define SM_ES   32768              // float es[2][64][72]    : 36864 B
#define SM_VS   69632              // float v_s[JT3]         : 4096 B
#define SM_RED1 73728              // float red1[128]        : 512 B
#define SM_RED2 74240              // float red2[128]        : 512 B
#define SM_TOT  74752

// ---------------- device scratch ----------------
__device__ float g_Wh[NN * FF];
__device__ float g_s1[NN];
__device__ float g_s2[NN];
__device__ float g_rs[PP * NN];
__device__ float g_cs[PP * NN];
__device__ __nv_bfloat16 g_whT_h[FF * NN];   // Wh^T bf16 hi [f][j]
__device__ __nv_bfloat16 g_whT_l[FF * NN];   // residual lo
__device__ float g_part[NSPLIT][NN * PP * FF];
__device__ float g_e[(size_t)PP * NN * NN];  // fallback e storage

__device__ __forceinline__ uint32_t smem_u32(const void* p) {
    uint32_t a;
    asm("{ .reg .u64 t; cvta.to.shared.u64 t, %1; cvt.u32.u64 %0, t; }" : "=r"(a) : "l"(p));
    return a;
}
__device__ __forceinline__ uint32_t swz(uint32_t o) { return o ^ ((o >> 3) & 0x70); }
__device__ __forceinline__ void cp_async16(uint32_t dst, const void* src) {
    asm volatile("cp.async.cg.shared.global [%0], [%1], 16;" :: "r"(dst), "l"(src) : "memory");
}
#define CP_COMMIT() asm volatile("cp.async.commit_group;" ::: "memory")
#define CP_WAIT(N)  asm volatile("cp.async.wait_group %0;" :: "n"(N) : "memory")
__device__ __forceinline__ void ldsm4(uint32_t& r0, uint32_t& r1, uint32_t& r2, uint32_t& r3,
                                      uint32_t addr) {
    asm volatile("ldmatrix.sync.aligned.m8n8.x4.shared.b16 {%0,%1,%2,%3}, [%4];"
                 : "=r"(r0), "=r"(r1), "=r"(r2), "=r"(r3) : "r"(addr));
}
#define MMA(c, a0, a1, a2, a3, b0, b1) \
    asm volatile("mma.sync.aligned.m16n8k16.row.col.f32.bf16.bf16.f32 " \
        "{%0,%1,%2,%3}, {%4,%5,%6,%7}, {%8,%9}, {%0,%1,%2,%3};" \
        : "+f"((c)[0]), "+f"((c)[1]), "+f"((c)[2]), "+f"((c)[3]) \
        : "r"(a0), "r"(a1), "r"(a2), "r"(a3), "r"(b0), "r"(b1))

// ---------------- kernel A: Wh = h @ W (+ splits, s1/s2, zero reductions) ----------------
__global__ void __launch_bounds__(256) k_wh(const float* __restrict__ h,
                                            const float* __restrict__ W,
                                            const float* __restrict__ a) {
    __shared__ float hs[32][INF_];
    __shared__ float red[8][8][2];
    int i0 = blockIdx.x * 32;
    int tid = threadIdx.x;
    if (blockIdx.x < 48) {
        int z = blockIdx.x * 256 + tid;
        g_rs[z] = 0.f; g_cs[z] = 0.f;
    }
    const float4* hg = (const float4*)(h + (size_t)i0 * INF_);
    float4* hs4 = (float4*)hs;
#pragma unroll
    for (int k = 0; k < 8; k++) hs4[tid + 256 * k] = hg[tid + 256 * k];
    __syncthreads();
    int f = tid & 63, ir = tid >> 6, lane = tid & 31, wrp = tid >> 5;
    float acc[8];
#pragma unroll
    for (int r = 0; r < 8; r++) acc[r] = 0.f;
    for (int k = 0; k < INF_; k++) {
        float wk = W[k * FF + f];
#pragma unroll
        for (int r = 0; r < 8; r++) acc[r] += hs[ir * 8 + r][k] * wk;
    }
    float a1 = a[f], a2 = a[FF + f];
#pragma unroll
    for (int r = 0; r < 8; r++) {
        int i = i0 + ir * 8 + r;
        g_Wh[(size_t)i * FF + f] = acc[r];
        __nv_bfloat16 hb = __float2bfloat16(acc[r]);
        g_whT_h[(size_t)f * NN + i] = hb;
        g_whT_l[(size_t)f * NN + i] = __float2bfloat16(acc[r] - __bfloat162float(hb));
        float p1 = acc[r] * a1, p2 = acc[r] * a2;
#pragma unroll
        for (int o = 16; o > 0; o >>= 1) {
            p1 += __shfl_down_sync(0xffffffffu, p1, o);
            p2 += __shfl_down_sync(0xffffffffu, p2, o);
        }
        if (lane == 0) { red[wrp][r][0] = p1; red[wrp][r][1] = p2; }
    }
    __syncthreads();
    if (tid < 32) {
        int irr = tid >> 3, r = tid & 7;
        g_s1[i0 + irr * 8 + r] = red[2 * irr][r][0] + red[2 * irr + 1][r][0];
        g_s2[i0 + irr * 8 + r] = red[2 * irr][r][1] + red[2 * irr + 1][r][1];
    }
}

// ---------------- kernel C: e + row/col sums (row-reduce hoisted out of loop) ----------------
__global__ void __launch_bounds__(256) k_pass1(const float* __restrict__ edge,
                                               float* __restrict__ e_out) {
    int p = blockIdx.y;
    int i0 = blockIdx.x * 16;
    int tid = threadIdx.x;
    const float4* s2v = (const float4*)g_s2;
    float4 s2r[3];
#pragma unroll
    for (int k = 0; k < 3; k++) s2r[k] = s2v[tid + 256 * k];
    float4 ca[3];
#pragma unroll
    for (int k = 0; k < 3; k++) ca[k] = make_float4(0.f, 0.f, 0.f, 0.f);
    float rsum[16];
#pragma unroll
    for (int r = 0; r < 16; r++) rsum[r] = 0.f;

    const float4* eg = (const float4*)(edge + (size_t)p * NN * NN);
    float4* eo = (float4*)(e_out + (size_t)p * NN * NN);

#pragma unroll 2
    for (int r = 0; r < 16; r++) {
        int i = i0 + r;
        float s1i = g_s1[i];
        size_t rb = (size_t)i * (NN / 4);
        float rp = 0.f;
#pragma unroll
        for (int k = 0; k < 3; k++) {
            float4 ea = eg[rb + tid + 256 * k];
            float4 s2q = s2r[k];
            float4 ev; float x;
            x = s1i + s2q.x; x = x > 0.f ? x : LALPHA * x; ev.x = x * ea.x;
            x = s1i + s2q.y; x = x > 0.f ? x : LALPHA * x; ev.y = x * ea.y;
            x = s1i + s2q.z; x = x > 0.f ? x : LALPHA * x; ev.z = x * ea.z;
            x = s1i + s2q.w; x = x > 0.f ? x : LALPHA * x; ev.w = x * ea.w;
            eo[rb + tid + 256 * k] = ev;
            rp += (ev.x + ev.y) + (ev.z + ev.w);
            ca[k].x += ev.x; ca[k].y += ev.y; ca[k].z += ev.z; ca[k].w += ev.w;
        }
        rsum[r] = rp;
    }
    // row reductions hoisted: no shfl chains in the streaming loop
#pragma unroll
    for (int r = 0; r < 16; r++) {
        float rp = rsum[r];
#pragma unroll
        for (int o = 16; o > 0; o >>= 1) rp += __shfl_down_sync(0xffffffffu, rp, o);
        if ((tid & 31) == 0) atomicAdd(&g_rs[p * NN + i0 + r], rp);
    }
#pragma unroll
    for (int k = 0; k < 3; k++) {
        int j = (tid + 256 * k) * 4;
        atomicAdd(&g_cs[p * NN + j + 0], ca[k].x);
        atomicAdd(&g_cs[p * NN + j + 1], ca[k].y);
        atomicAdd(&g_cs[p * NN + j + 2], ca[k].z);
        atomicAdd(&g_cs[p * NN + j + 3], ca[k].w);
    }
}

// ---------------- kernel E: cp.async-staged e + B, mma.sync GEMM, j-split x3 ----------------
// grid (48, 4, 3), 128 threads = 4 warps; inline scalar reduction; dynamic smem SM_TOT.
__global__ void __launch_bounds__(128) k_pass2p(const float* __restrict__ e_in,
                                                float* __restrict__ part) {
    extern __shared__ __align__(16) char smem[];
    float* v_s  = (float*)(smem + SM_VS);
    float* red1 = (float*)(smem + SM_RED1);
    float* red2 = (float*)(smem + SM_RED2);

    int tid = threadIdx.x, lane = tid & 31, w = tid >> 5;
    int p = blockIdx.y, i0 = blockIdx.x * 64;
    int third = blockIdx.z;
    int j0 = third * JT3;

    int g = lane >> 2, q = (lane & 3) * 2;
    int r0 = w * 16 + g, r1 = r0 + 8;        // local rows
    int row0 = i0 + r0;

    int brow = (lane & 7) + ((lane >> 1) & 8);
    int bk = ((lane >> 3) & 1) * 8;
    uint32_t sb = smem_u32(smem);
    const float* egbase = e_in + (size_t)p * NN * NN + (size_t)i0 * NN + j0;

// stage B (16KB) and e (16KB->18KB padded) for chunk cc into buffer cc&1, one commit group
#define STAGE(cc) do { \
    uint32_t stB = sb + (((cc) & 1) ? 16384u : 0u); \
    uint32_t stE = sb + SM_ES + (((cc) & 1) ? 18432u : 0u); \
    _Pragma("unroll") \
    for (int t = 0; t < 4; t++) { \
        int s = tid + t * 128; \
        int fr = s >> 3, col = s & 7; \
        uint32_t o = swz((uint32_t)(fr * 128 + col * 16)); \
        cp_async16(stB + o,        g_whT_h + (size_t)fr * NN + j0 + (cc) * 64 + col * 8); \
        cp_async16(stB + 8192 + o, g_whT_l + (size_t)fr * NN + j0 + (cc) * 64 + col * 8); \
    } \
    _Pragma("unroll") \
    for (int t = 0; t < 8; t++) { \
        int s = tid + t * 128; \
        int row = s >> 4, c = s & 15; \
        cp_async16(stE + (uint32_t)((row * 72 + c * 4) * 4), \
                   egbase + (size_t)row * NN + (cc) * 64 + c * 4); \
    } \
    CP_COMMIT(); \
} while (0)

    STAGE(NCHUNK - 1);   // overlap first prefetch with the scalar reduction below

    // ---- inline scalar reduction: lamb = max(rs,cs), r = N*lamb - sum(rs) ----
    {
        float mx = -1e30f, sm = 0.f;
#pragma unroll
        for (int k = tid; k < NN; k += 128) {
            float rv = g_rs[p * NN + k];
            float cv = g_cs[p * NN + k];
            mx = fmaxf(mx, fmaxf(rv, cv));
            sm += rv;
        }
        red1[tid] = mx; red2[tid] = sm;
        __syncthreads();
        for (int s = 64; s > 0; s >>= 1) {
            if (tid < s) { red1[tid] = fmaxf(red1[tid], red1[tid + s]); red2[tid] += red2[tid + s]; }
            __syncthreads();
        }
    }
    float lamb = red1[0];
    float inv_r = 1.f / ((float)NN * lamb - red2[0]);
    float inv_l = 1.f / lamb;   // analytic: col-normalizer == lamb

    float u0 = (lamb - g_rs[p * NN + row0]) * inv_r;
    float u1 = (lamb - g_rs[p * NN + row0 + 8]) * inv_r;

    // stage v for this j-third: v = (lamb - cs) * inv_l
#pragma unroll
    for (int t = tid; t < JT3; t += 128)
        v_s[t] = (lamb - g_cs[p * NN + j0 + t]) * inv_l;

    float cacc[8][4];
#pragma unroll
    for (int n = 0; n < 8; n++)
#pragma unroll
        for (int r = 0; r < 4; r++) cacc[n][r] = 0.f;

    // reverse order: read e newest-first to catch pass1's tail in L2
    for (int ch = NCHUNK - 1; ch >= 0; ch--) {
        if (ch > 0) { STAGE(ch - 1); CP_WAIT(1); }
        else        { CP_WAIT(0); }
        __syncthreads();

        uint32_t sbase = sb + ((ch & 1) ? 16384u : 0u);
        const float* esp = (const float*)(smem + SM_ES + ((ch & 1) ? 18432 : 0));
#pragma unroll
        for (int ks = 0; ks < 4; ks++) {
            int kb = ch * 64 + ks * 16;
            int kl = ks * 16;
            float2 e00 = *(const float2*)&esp[r0 * 72 + kl + q];
            float2 e10 = *(const float2*)&esp[r1 * 72 + kl + q];
            float2 e01 = *(const float2*)&esp[r0 * 72 + kl + q + 8];
            float2 e11 = *(const float2*)&esp[r1 * 72 + kl + q + 8];
            float2 vA = *(const float2*)&v_s[kb + q];
            float2 vB = *(const float2*)&v_s[kb + q + 8];
            float a00 = e00.x > 0.f ? fmaf(u0, vA.x, e00.x * inv_l) : e00.x;
            float a01 = e00.y > 0.f ? fmaf(u0, vA.y, e00.y * inv_l) : e00.y;
            float a10 = e10.x > 0.f ? fmaf(u1, vA.x, e10.x * inv_l) : e10.x;
            float a11 = e10.y > 0.f ? fmaf(u1, vA.y, e10.y * inv_l) : e10.y;
            float a02 = e01.x > 0.f ? fmaf(u0, vB.x, e01.x * inv_l) : e01.x;
            float a03 = e01.y > 0.f ? fmaf(u0, vB.y, e01.y * inv_l) : e01.y;
            float a12 = e11.x > 0.f ? fmaf(u1, vB.x, e11.x * inv_l) : e11.x;
            float a13 = e11.y > 0.f ? fmaf(u1, vB.y, e11.y * inv_l) : e11.y;
            uint32_t ah0, ah1, ah2, ah3, al0, al1, al2, al3;
            asm("cvt.rn.bf16x2.f32 %0, %1, %2;" : "=r"(ah0) : "f"(a01), "f"(a00));
            asm("cvt.rn.bf16x2.f32 %0, %1, %2;" : "=r"(ah1) : "f"(a11), "f"(a10));
            asm("cvt.rn.bf16x2.f32 %0, %1, %2;" : "=r"(ah2) : "f"(a03), "f"(a02));
            asm("cvt.rn.bf16x2.f32 %0, %1, %2;" : "=r"(ah3) : "f"(a13), "f"(a12));
            float r00 = a00 - __uint_as_float(ah0 << 16);
            float r01 = a01 - __uint_as_float(ah0 & 0xffff0000u);
            float r10 = a10 - __uint_as_float(ah1 << 16);
            float r11 = a11 - __uint_as_float(ah1 & 0xffff0000u);
            float r02 = a02 - __uint_as_float(ah2 << 16);
            float r03 = a03 - __uint_as_float(ah2 & 0xffff0000u);
            float r12 = a12 - __uint_as_float(ah3 << 16);
            float r13 = a13 - __uint_as_float(ah3 & 0xffff0000u);
            asm("cvt.rn.bf16x2.f32 %0, %1, %2;" : "=r"(al0) : "f"(r01), "f"(r00));
            asm("cvt.rn.bf16x2.f32 %0, %1, %2;" : "=r"(al1) : "f"(r11), "f"(r10));
            asm("cvt.rn.bf16x2.f32 %0, %1, %2;" : "=r"(al2) : "f"(r03), "f"(r02));
            asm("cvt.rn.bf16x2.f32 %0, %1, %2;" : "=r"(al3) : "f"(r13), "f"(r12));

            uint32_t lof = (uint32_t)(brow * 128 + (ks * 16 + bk) * 2);
#pragma unroll
            for (int np = 0; np < 4; np++) {
                uint32_t off = swz(lof + np * 2048);
                uint32_t bh0, bh1, bh2, bh3, bl0, bl1, bl2, bl3;
                ldsm4(bh0, bh1, bh2, bh3, sbase + off);
                ldsm4(bl0, bl1, bl2, bl3, sbase + 8192 + off);
                MMA(cacc[2 * np],     ah0, ah1, ah2, ah3, bh0, bh1);
                MMA(cacc[2 * np],     al0, al1, al2, al3, bh0, bh1);
                MMA(cacc[2 * np],     ah0, ah1, ah2, ah3, bl0, bl1);
                MMA(cacc[2 * np + 1], ah0, ah1, ah2, ah3, bh2, bh3);
                MMA(cacc[2 * np + 1], al0, al1, al2, al3, bh2, bh3);
                MMA(cacc[2 * np + 1], ah0, ah1, ah2, ah3, bl2, bl3);
            }
        }
        __syncthreads();
    }

    // ---- store partials ----
    float* o0 = part + (size_t)third * (NN * PP * FF)
              + (size_t)row0 * (PP * FF) + p * FF + q;
    float* o1 = o0 + (size_t)8 * (PP * FF);
#pragma unroll
    for (int n = 0; n < 8; n++) {
        *(float2*)(o0 + n * 8) = make_float2(cacc[n][0], cacc[n][1]);
        *(float2*)(o1 + n * 8) = make_float2(cacc[n][2], cacc[n][3]);
    }
#undef STAGE
}

// ---------------- kernel F: combine thirds + elu ----------------
__global__ void __launch_bounds__(256) k_elu(const float* __restrict__ part,
                                             float* __restrict__ out0) {
    int i = blockIdx.x * 256 + threadIdx.x;
    float4 a = ((const float4*)part)[i];
    float4 b = ((const float4*)(part + (size_t)NN * PP * FF))[i];
    float4 c = ((const float4*)(part + (size_t)2 * NN * PP * FF))[i];
    float4 v;
    v.x = a.x + b.x + c.x; v.y = a.y + b.y + c.y;
    v.z = a.z + b.z + c.z; v.w = a.w + b.w + c.w;
    v.x = v.x > 0.f ? v.x : expm1f(v.x);
    v.y = v.y > 0.f ? v.y : expm1f(v.y);
    v.z = v.z > 0.f ? v.z : expm1f(v.z);
    v.w = v.w > 0.f ? v.w : expm1f(v.w);
    ((float4*)out0)[i] = v;
}

// ---------------- launch ----------------
extern "C" void kernel_launch(void* const* d_in, const int* in_sizes, int n_in,
                              void* d_out, int out_size) {
    const float* h    = (const float*)d_in[0];
    const float* edge = (const float*)d_in[1];
    const float* W    = (const float*)d_in[2];
    const float* a    = (const float*)d_in[3];
    float* out = (float*)d_out;

    float* e_dst;
    long long need = (long long)NN * PP * FF + (long long)PP * NN * NN;
    if ((long long)out_size >= need) {
        e_dst = out + (size_t)NN * PP * FF;
    } else {
        void* pe = nullptr;
        cudaGetSymbolAddress(&pe, g_e);
        e_dst = (float*)pe;
    }
    void* ppart = nullptr;
    cudaGetSymbolAddress(&ppart, g_part);
    float* part = (float*)ppart;

    static bool attr_done = false;
    if (!attr_done) {
        cudaFuncSetAttribute(k_pass2p, cudaFuncAttributeMaxDynamicSharedMemorySize, SM_TOT);
        attr_done = true;
    }

    k_wh<<<NN / 32, 256>>>(h, W, a);
    k_pass1<<<dim3(NN / 16, PP), 256>>>(edge, e_dst);
    k_pass2p<<<dim3(NN / 64, PP, NSPLIT), 128, SM_TOT>>>(e_dst, part);
    k_elu<<<(NN * PP * FF / 4 + 255) / 256, 256>>>(part, out);
}